// round 14
// baseline (speedup 1.0000x reference)
#include <cuda_runtime.h>
#include <cuda_fp16.h>
#include <math.h>
#include <stdint.h>

// ============================================================================
// Problem constants
// ============================================================================
namespace {
constexpr int B_ = 8, C_ = 512, L_ = 256;
constexpr int CL_ = C_ * L_;           // 131072
constexpr int C3_ = 3 * C_;            // 1536
constexpr int C4_ = 4 * C_;            // 2048
constexpr int NR_ = L_ * B_;           // 2048
constexpr size_t BLL_ = (size_t)B_ * L_ * L_;
constexpr float SCALE_ = 0.044194173824159216f; // 512^-0.5

// ---------------- scratch offsets (float units) ----------------
constexpr size_t OFF_XT_HI   = 0;                                    // f16 [B,L,C]
constexpr size_t OFF_XT32    = OFF_XT_HI   + (size_t)B_ * CL_ / 2;   // f32 [B,L,C]
constexpr size_t OFF_WQKV_HI = OFF_XT32    + (size_t)B_ * CL_;       // f16 [3C,C]
constexpr size_t OFF_QKV_B   = OFF_WQKV_HI + (size_t)C3_ * C_ / 2;   // f32 [1536]
constexpr size_t OFF_WWG_HI  = OFF_QKV_B   + 1536;
constexpr size_t OFF_C1WHI   = OFF_WWG_HI  + (size_t)C_ * C_ / 2;
constexpr size_t OFF_C2WHI   = OFF_C1WHI   + (size_t)C4_ * C_ / 2;
constexpr size_t OFF_QKVT_HI = OFF_C2WHI   + (size_t)C_ * C4_ / 2;   // f16 [B,L,3C]
constexpr size_t OFF_SG      = OFF_QKVT_HI + (size_t)B_ * L_ * C3_ / 2; // f32 [2][B,L,L]
constexpr size_t OFF_GP_HI   = OFF_SG      + 2 * BLL_;               // f16 [B,L,L]
constexpr size_t OFF_GG2_HI  = OFF_GP_HI   + BLL_ / 2;               // f16 [B,C,L]
constexpr size_t OFF_GBAR    = OFF_GG2_HI  + (size_t)B_ * CL_ / 2;
constexpr size_t OFF_GATE    = OFF_GBAR    + (size_t)B_ * L_;
constexpr size_t OFF_GOUTT_HI= OFF_GATE    + (size_t)B_ * L_;        // f16 [B,L,C]
constexpr size_t OFF_GOUT2T  = OFF_GOUTT_HI+ (size_t)B_ * CL_ / 2;   // f32 [B,L,C]
constexpr size_t OFF_H1      = OFF_GOUT2T  + (size_t)B_ * CL_;       // f32 [NR,C]
constexpr size_t OFF_H1HI    = OFF_H1      + (size_t)NR_ * C_;       // f16 [NR,C]
constexpr size_t OFF_M1HI    = OFF_H1HI    + (size_t)NR_ * C_ / 2;   // f16 [NR,C4]
constexpr size_t OFF_M2      = OFF_M1HI    + (size_t)NR_ * C4_ / 2;  // f32 [NR,C]
constexpr size_t SCRATCH_TOTAL = OFF_M2    + (size_t)NR_ * C_;
} // namespace

__device__ __align__(256) float d_scratch[SCRATCH_TOTAL];
__device__ unsigned int d_bar_count = 0;
__device__ unsigned int d_bar_gen = 0;

// ============================================================================
// PTX helpers — sm_80-era only (mma.sync / ldmatrix / cp.async).
// ============================================================================
__device__ __forceinline__ uint32_t smem_to_u32(const void* p) {
    uint32_t a;
    asm("{ .reg .u64 t; cvta.to.shared.u64 t, %1; cvt.u32.u64 %0, t; }" : "=r"(a) : "l"(p));
    return a;
}
__device__ __forceinline__ void ldmat4(uint32_t (&r)[4], uint32_t addr) {
    asm volatile("ldmatrix.sync.aligned.m8n8.x4.shared.b16 {%0,%1,%2,%3}, [%4];"
                 : "=r"(r[0]), "=r"(r[1]), "=r"(r[2]), "=r"(r[3]) : "r"(addr));
}
__device__ __forceinline__ void mma16816(float (&d)[4], const uint32_t (&a)[4], const uint32_t b0, const uint32_t b1) {
    asm volatile("mma.sync.aligned.m16n8k16.row.col.f32.f16.f16.f32 "
                 "{%0,%1,%2,%3}, {%4,%5,%6,%7}, {%8,%9}, {%0,%1,%2,%3};"
                 : "+f"(d[0]), "+f"(d[1]), "+f"(d[2]), "+f"(d[3])
                 : "r"(a[0]), "r"(a[1]), "r"(a[2]), "r"(a[3]), "r"(b0), "r"(b1));
}
__device__ __forceinline__ void cp16(uint32_t saddr, const void* g) {
    asm volatile("cp.async.cg.shared.global [%0], [%1], 16;" :: "r"(saddr), "l"(g));
}
#define CP_COMMIT() asm volatile("cp.async.commit_group;" ::: "memory")
template <int N>
__device__ __forceinline__ void cp_wait() {
    asm volatile("cp.async.wait_group %0;" :: "n"(N) : "memory");
}

namespace {

__device__ __forceinline__ float warpSum(float v) {
#pragma unroll
    for (int o = 16; o; o >>= 1) v += __shfl_xor_sync(0xffffffffu, v, o);
    return v;
}
__device__ __forceinline__ float warpMax(float v) {
#pragma unroll
    for (int o = 16; o; o >>= 1) v = fmaxf(v, __shfl_xor_sync(0xffffffffu, v, o));
    return v;
}
__device__ __forceinline__ float mishf(float v) {
    float sp = fmaxf(v, 0.f) + log1pf(__expf(-fabsf(v)));
    return v * tanhf(sp);
}

// ---------------- software grid barrier (write-once dataflow + cp.cg make it safe)
__device__ __forceinline__ void gsync(int ncta) {
    __syncthreads();
    if (threadIdx.x == 0) {
        volatile unsigned* vgen = &d_bar_gen;
        unsigned gen = *vgen;
        __threadfence();
        if (atomicAdd(&d_bar_count, 1u) == (unsigned)(ncta - 1)) {
            d_bar_count = 0;
            __threadfence();
            *vgen = gen + 1u;
        } else {
            while (*vgen == gen) { __nanosleep(64); }
        }
        __threadfence();
    }
    __syncthreads();
}

// ============================================================================
// fp16 tensor-core GEMM body (virtual-block form). 1-pass fp16 NT:
//   A [M,K] K-contig (lda) ; B [N,K] K-contig (ldb). D = A·B^T (fp32 accum).
// v = scale*D (+ biasN); ACT=1 -> mish. OUTFMT 0: f32 ; 2: f16.
// FUSE=1: zz encodes (sel = zz>>3, b = zz&7).
// ============================================================================
template <int BN, int OUTFMT, int ACT, int FUSE, int STAGES, int KB, int WM>
__device__ __forceinline__ void gemm_body(
    int bx, int by, int zz,
    const __half* __restrict__ A, const __half* __restrict__ Bm,
    const float* __restrict__ biasN,
    float* __restrict__ outF, __half* __restrict__ outH,
    int K, int lda, int ldb, int ldOut,
    size_t sA, size_t sB, size_t sO, size_t selB, size_t selO, float scale,
    char* smem)
{
    constexpr int BM = 128;
    constexpr int TPB = WM * 128;
    constexpr int MI = BM / (WM * 16);
    constexpr int SROW = KB * 2 + 16;
    constexpr int CHR = KB / 8;
    constexpr int ATILE = BM * SROW;
    constexpr int BTILE = BN * SROW;
    constexpr int STAGE = ATILE + BTILE;
    constexpr int WN = BN / 4;
    constexpr int NFRAG = WN / 8;
    constexpr int NKS = KB / 16;

    const uint32_t sb = smem_to_u32(smem);
    const int tid = threadIdx.x, lane = tid & 31, wid = tid >> 5;
    const int wm = wid & (WM - 1), wn = wid / WM;
    const int m0 = by * BM, n0 = bx * BN;
    const int b = FUSE ? (zz & 7) : zz;
    const int sel = FUSE ? (zz >> 3) : 0;

    A += (size_t)b * sA;
    Bm += (size_t)b * sB + (size_t)sel * selB;
    if (OUTFMT == 0) outF += (size_t)b * sO + (size_t)sel * selO;
    else             outH += (size_t)b * sO + (size_t)sel * selO;

    float acc[MI][NFRAG][4];
#pragma unroll
    for (int i = 0; i < MI; i++)
#pragma unroll
        for (int j = 0; j < NFRAG; j++)
#pragma unroll
            for (int q = 0; q < 4; q++) acc[i][j][q] = 0.f;

    auto load_stage = [&](int ch, int st) {
        const int k0 = ch * KB;
        const uint32_t base = sb + st * STAGE;
#pragma unroll
        for (int c = tid; c < BM * CHR; c += TPB) {
            int r = c / CHR, cc = c % CHR;
            cp16(base + r * SROW + cc * 16, A + (size_t)(m0 + r) * lda + k0 + cc * 8);
        }
#pragma unroll
        for (int c = tid; c < BN * CHR; c += TPB) {
            int r = c / CHR, cc = c % CHR;
            cp16(base + ATILE + r * SROW + cc * 16, Bm + (size_t)(n0 + r) * ldb + k0 + cc * 8);
        }
        CP_COMMIT();
    };

    const int nch = K / KB;
#pragma unroll
    for (int s = 0; s < STAGES - 1; s++) load_stage(s, s);

    int cs = 0;
    int ps = (STAGES - 1) % STAGES;
    for (int ch = 0; ch < nch; ch++) {
        cp_wait<STAGES - 2>();
        __syncthreads();
        const int pf = ch + STAGES - 1;
        if (pf < nch) load_stage(pf, ps);
        else CP_COMMIT();

        const uint32_t aBase = sb + cs * STAGE;
        const uint32_t bBase = aBase + ATILE;
#pragma unroll
        for (int ks = 0; ks < NKS; ks++) {
            const uint32_t colOff = (uint32_t)(ks * 2 + (lane >> 4)) * 16;
            uint32_t a_f[MI][4];
#pragma unroll
            for (int mi = 0; mi < MI; mi++) {
                uint32_t addr = aBase + (uint32_t)(wm * (MI * 16) + mi * 16 + (lane & 15)) * SROW + colOff;
                ldmat4(a_f[mi], addr);
            }
#pragma unroll
            for (int nt = 0; nt < NFRAG / 2; nt++) {
                uint32_t addr = bBase + (uint32_t)(wn * WN + nt * 16 + (lane & 15)) * SROW + colOff;
                uint32_t bf[4];
                ldmat4(bf, addr);
#pragma unroll
                for (int half = 0; half < 2; half++) {
                    const int ni = nt * 2 + half;
#pragma unroll
                    for (int mi = 0; mi < MI; mi++)
                        mma16816(acc[mi][ni], a_f[mi], bf[half], bf[2 + half]);
                }
            }
        }
        cs = (cs + 1 == STAGES) ? 0 : cs + 1;
        ps = (ps + 1 == STAGES) ? 0 : ps + 1;
    }
    cp_wait<0>();
    __syncthreads();   // all warps done with SMEM before caller reuses it

    // ---------------- epilogue (registers + global only) ----------------
    const int g = lane >> 2, tg = lane & 3;
#pragma unroll
    for (int mi = 0; mi < MI; mi++) {
#pragma unroll
        for (int ni = 0; ni < NFRAG; ni++) {
            const int col = n0 + wn * WN + ni * 8 + tg * 2;
            const float b0 = biasN ? biasN[col] : 0.f;
            const float b1 = biasN ? biasN[col + 1] : 0.f;
#pragma unroll
            for (int h = 0; h < 2; h++) {
                const int row = m0 + wm * (MI * 16) + mi * 16 + g + h * 8;
                float v0 = acc[mi][ni][h * 2 + 0] * scale + b0;
                float v1 = acc[mi][ni][h * 2 + 1] * scale + b1;
                if (ACT == 1) { v0 = mishf(v0); v1 = mishf(v1); }
                const size_t o = (size_t)row * ldOut + col;
                if (OUTFMT == 0) {
                    float2 fp; fp.x = v0; fp.y = v1;
                    *(float2*)(outF + o) = fp;
                } else {
                    __half2 hp;
                    hp.x = __float2half_rn(v0);
                    hp.y = __float2half_rn(v1);
                    *(__half2*)(outH + o) = hp;
                }
            }
        }
    }
}

// ---------------- phase tile counts ----------------
constexpr int PREP_WELEMS = 3 * C_ * C_ + C_ * C_ + C4_ * C_ + C_ * C4_;  // 3145728
constexpr int PREP_NW8 = PREP_WELEMS / 8 / 256;       // 1536
constexpr int PREP_NB = 6;
constexpr int PREP_NT = (L_ / 32) * (C_ / 32) * B_;   // 1024
constexpr int PREP_TOTAL = PREP_NW8 + PREP_NB + PREP_NT;
constexpr int QKV_TILES  = 12 * 2 * 8;                // 192
constexpr int SGSL_GEMM  = 4 * 2 * 16;                // 128
constexpr int SGSL_TOTAL = SGSL_GEMM + 64;            // +transpose
constexpr int SMAX_TILES = 32 * 8;                    // 256
constexpr int GW_TILES   = 8 * 2 * 8;                 // 128 (gout and wg)
constexpr int LN_TILES   = NR_;                       // 2048
constexpr int MLP1_TILES = 16 * 16;                   // 256
constexpr int MLP2_TILES = 8 * 16;                    // 128

// ============================================================================
// MEGA KERNEL: whole pipeline, persistent CTAs, software grid barriers.
// ============================================================================
__global__ void __launch_bounds__(256, 2) mega_kernel(
    const float* __restrict__ x,
    const float* __restrict__ tw, const float* __restrict__ pw,
    const float* __restrict__ gw, const float* __restrict__ wgw,
    const float* __restrict__ c1w, const float* __restrict__ c2w,
    const float* __restrict__ tb, const float* __restrict__ pb,
    const float* __restrict__ gb,
    const float* __restrict__ wlw, const float* __restrict__ wlb,
    const float* __restrict__ wgb,
    const float* __restrict__ c1b, const float* __restrict__ c2b,
    const float* __restrict__ ln1g, const float* __restrict__ ln1b,
    const float* __restrict__ ln2g, const float* __restrict__ ln2b,
    float* __restrict__ out, int ncta)
{
    extern __shared__ char smem[];
    float* scr = d_scratch;
    __half* xtHi   = (__half*)(scr + OFF_XT_HI);
    float*  xt32   = scr + OFF_XT32;
    __half* qkvW   = (__half*)(scr + OFF_WQKV_HI);
    float*  qkv_b  = scr + OFF_QKV_B;
    __half* wgW    = (__half*)(scr + OFF_WWG_HI);
    __half* c1W    = (__half*)(scr + OFF_C1WHI);
    __half* c2W    = (__half*)(scr + OFF_C2WHI);
    __half* qkvHi  = (__half*)(scr + OFF_QKVT_HI);
    float*  Sg     = scr + OFF_SG;
    float*  Sl     = Sg + BLL_;
    __half* gpHi   = (__half*)(scr + OFF_GP_HI);
    __half* gg2Hi  = (__half*)(scr + OFF_GG2_HI);
    float*  gbar   = scr + OFF_GBAR;
    float*  gate   = scr + OFF_GATE;
    __half* goHi   = (__half*)(scr + OFF_GOUTT_HI);
    float*  gout2T = scr + OFF_GOUT2T;
    float*  h1     = scr + OFF_H1;
    __half* h1Hi   = (__half*)(scr + OFF_H1HI);
    __half* m1Hi   = (__half*)(scr + OFF_M1HI);
    float*  m2     = scr + OFF_M2;

    const int rank = blockIdx.x;
    const int tid = threadIdx.x;
    const int lane = tid & 31, w = tid >> 5;

    // ======== P0: prep (weights f16, bias concat, x transpose) ========
    for (int vb = rank; vb < PREP_TOTAL; vb += ncta) {
        if (vb < PREP_NW8) {
            constexpr int NW = C_ * C_;
            constexpr int N1 = 3 * NW;
            constexpr int N2 = N1 + NW;
            constexpr int N3 = N2 + C4_ * C_;
            const int i = (vb * 256 + tid) * 8;
            const float* src;
            __half* dst;
            int j;
            if (i < N1) {
                j = i & (NW - 1);
                src = (i < NW) ? tw : (i < 2 * NW ? pw : gw);
                dst = qkvW + i;
            } else if (i < N2) { j = i - N1; src = wgw; dst = wgW + j; }
            else if (i < N3)   { j = i - N2; src = c1w; dst = c1W + j; }
            else               { j = i - N3; src = c2w; dst = c2W + j; }
            float4 va = *(const float4*)(src + j);
            float4 vb4 = *(const float4*)(src + j + 4);
            __half2 h[4];
            h[0].x = __float2half_rn(va.x);  h[0].y = __float2half_rn(va.y);
            h[1].x = __float2half_rn(va.z);  h[1].y = __float2half_rn(va.w);
            h[2].x = __float2half_rn(vb4.x); h[2].y = __float2half_rn(vb4.y);
            h[3].x = __float2half_rn(vb4.z); h[3].y = __float2half_rn(vb4.w);
            *(uint4*)dst = *(uint4*)h;
        } else if (vb < PREP_NW8 + PREP_NB) {
            const int j = (vb - PREP_NW8) * 256 + tid;
            if (j < C3_)
                qkv_b[j] = (j < C_) ? tb[j] : (j < 2 * C_ ? pb[j - C_] : gb[j - 2 * C_]);
        } else {
            float (*t)[33] = (float(*)[33])smem;
            const int tI = vb - PREP_NW8 - PREP_NB;
            const int b = tI >> 7;
            const int rem = tI & 127;
            const int c0 = (rem & 15) * 32;
            const int l0 = (rem >> 4) * 32;
            const int tx = lane, ty = w;
            const float* xb = x + (size_t)b * CL_;
#pragma unroll
            for (int j = 0; j < 4; j++)
                t[ty + j * 8][tx] = xb[(size_t)(c0 + ty + j * 8) * L_ + l0 + tx];
            __syncthreads();
#pragma unroll
            for (int j = 0; j < 4; j++) {
                int l = l0 + ty + j * 8;
                float v = t[tx][ty + j * 8];
                size_t o = ((size_t)b * L_ + l) * C_ + c0 + tx;
                xtHi[o] = __float2half_rn(v);
                xt32[o] = v;
            }
            __syncthreads();
        }
    }
    gsync(ncta);

    // ======== P1: qkv GEMM (192 tiles, BN=128 KB=32 2st) ========
    for (int vb = rank; vb < QKV_TILES; vb += ncta) {
        gemm_body<128, 2, 0, 0, 2, 32, 2>(
            vb % 12, (vb / 12) % 2, vb / 24,
            xtHi, qkvW, qkv_b, nullptr, qkvHi,
            C_, C_, C_, C3_, (size_t)L_ * C_, 0, (size_t)L_ * C3_, 0, 0, 1.f, smem);
    }
    gsync(ncta);

    // ======== P2: Sg/Sl GEMM (128) + g-transpose/gbar (64) ========
    for (int vb = rank; vb < SGSL_TOTAL; vb += ncta) {
        if (vb < SGSL_GEMM) {
            gemm_body<64, 0, 0, 1, 3, 64, 2>(
                vb % 4, (vb / 4) % 2, vb / 8,
                qkvHi + C_, qkvHi, nullptr, Sg, nullptr,
                C_, C3_, C3_, L_, (size_t)L_ * C3_, (size_t)L_ * C3_, (size_t)L_ * L_,
                (size_t)(2 * C_), BLL_, SCALE_, smem);
        } else {
            __half (*th)[34] = (__half(*)[34])smem;
            const int tv = vb - SGSL_GEMM;
            const int b = tv >> 3;
            const int l0 = (tv & 7) * 32;
            const int tx = lane, ty = w;
            for (int ct = 0; ct < 16; ct++) {
                const int c0 = ct * 32;
#pragma unroll
                for (int j = 0; j < 4; j++) {
                    size_t idx = ((size_t)b * L_ + l0 + ty + j * 8) * C3_ + 2 * C_ + c0 + tx;
                    th[ty + j * 8][tx] = qkvHi[idx];
                }
                __syncthreads();
#pragma unroll
                for (int j = 0; j < 4; j++) {
                    int c = c0 + ty + j * 8;
                    size_t o = ((size_t)b * C_ + c) * L_ + l0 + tx;
                    gg2Hi[o] = th[tx][ty + j * 8];
                }
                __syncthreads();
            }
#pragma unroll
            for (int i = 0; i < 4; i++) {
                const int l = l0 + ty * 4 + i;
                const size_t base = ((size_t)b * L_ + l) * C3_ + 2 * C_;
                float s = 0.f;
#pragma unroll
                for (int c = tx; c < C_; c += 32)
                    s += __half2float(qkvHi[base + c]);
                s = warpSum(s);
                if (tx == 0) gbar[b * L_ + l] = s * (1.f / C_);
            }
        }
    }
    gsync(ncta);

    // ======== P3: softmax + local gate (warp-per-row; no smem) ========
    for (int vb = rank; vb < SMAX_TILES; vb += ncta) {
        const int b = vb / 32;
        const int l = (vb % 32) * 8 + w;
        const size_t row = (size_t)b * L_ + l;
        const float4* srow4 = (const float4*)(Sg + row * L_);
        float4 a4 = srow4[lane * 2];
        float4 c4 = srow4[lane * 2 + 1];
        float v[8] = {a4.x, a4.y, a4.z, a4.w, c4.x, c4.y, c4.z, c4.w};
        float mx = v[0];
#pragma unroll
        for (int i = 1; i < 8; i++) mx = fmaxf(mx, v[i]);
        mx = warpMax(mx);
        float sum = 0.f;
#pragma unroll
        for (int i = 0; i < 8; i++) { v[i] = __expf(v[i] - mx); sum += v[i]; }
        sum = warpSum(sum);
        const float inv = 1.f / sum;
        __half2 hp[4];
#pragma unroll
        for (int i = 0; i < 4; i++) {
            hp[i].x = __float2half_rn(v[2 * i] * inv);
            hp[i].y = __float2half_rn(v[2 * i + 1] * inv);
        }
        *(uint4*)(gpHi + row * L_ + lane * 8) = *(uint4*)hp;

        const float* slrow = Sl + row * L_;
        const float* gbr = gbar + (size_t)b * L_;
        int m0 = l + lane - 32;
        int m1 = l + lane;
        bool v0 = (m0 >= 0) && (m0 < L_);
        bool v1 = (m1 >= 0) && (m1 < L_);
        float s0 = v0 ? slrow[m0] : 0.f;
        float s1 = v1 ? slrow[m1] : 0.f;
        float g0 = v0 ? gbr[m0] : 0.f;
        float g1 = v1 ? gbr[m1] : 0.f;
        float bx2 = warpMax(fmaxf(s0, s1));
        float e0 = __expf(s0 - bx2), e1 = __expf(s1 - bx2);
        float num = warpSum(e0 * g0 + e1 * g1);
        float den = warpSum(e0 + e1);
        if (lane == 0) {
            float pooled = num / den;
            float z = wlw[0] * pooled + wlb[0];
            gate[b * L_ + l] = 1.f / (1.f + __expf(-z));
        }
    }
    gsync(ncta);

    // ======== P4: gout GEMM (128 tiles) ========
    for (int vb = rank; vb < GW_TILES; vb += ncta) {
        gemm_body<64, 2, 0, 0, 3, 64, 2>(
            vb % 8, (vb / 8) % 2, vb / 16,
            gpHi, gg2Hi, nullptr, nullptr, goHi,
            L_, L_, L_, C_, (size_t)L_ * L_, (size_t)CL_, (size_t)L_ * C_, 0, 0, 1.f, smem);
    }
    gsync(ncta);

    // ======== P5: wg GEMM (128 tiles) ========
    for (int vb = rank; vb < GW_TILES; vb += ncta) {
        gemm_body<64, 0, 0, 0, 3, 64, 2>(
            vb % 8, (vb / 8) % 2, vb / 16,
            goHi, wgW, wgb, gout2T, nullptr,
            C_, C_, C_, C_, (size_t)L_ * C_, 0, (size_t)L_ * C_, 0, 0, 1.f, smem);
    }
    gsync(ncta);

    // ======== P6: LN1 (2048 rows) ========
    {
        __shared__ float sm1[16];
        for (int vb = rank; vb < LN_TILES; vb += ncta) {
            const int l = vb & 255, b = vb >> 8;
            float gt = gate[b * L_ + l];
            size_t gbase = ((size_t)b * L_ + l) * C_;
            float v0 = fmaf(gout2T[gbase + tid], gt, xt32[gbase + tid]);
            float v1 = fmaf(gout2T[gbase + tid + 256], gt, xt32[gbase + tid + 256]);
            float s = warpSum(v0 + v1);
            float q = warpSum(v0 * v0 + v1 * v1);
            if (lane == 0) { sm1[w] = s; sm1[8 + w] = q; }
            __syncthreads();
            float S = 0.f, Q = 0.f;
#pragma unroll
            for (int i = 0; i < 8; i++) { S += sm1[i]; Q += sm1[8 + i]; }
            float mean = S * (1.f / C_);
            float var = Q * (1.f / C_) - mean * mean;
            float r = rsqrtf(var + 1e-5f);
            size_t o = ((size_t)l * B_ + b) * C_;
            float y0 = (v0 - mean) * r * ln1g[tid] + ln1b[tid];
            float y1 = (v1 - mean) * r * ln1g[tid + 256] + ln1b[tid + 256];
            h1[o + tid] = y0;
            h1[o + tid + 256] = y1;
            h1Hi[o + tid] = __float2half_rn(y0);
            h1Hi[o + tid + 256] = __float2half_rn(y1);
            __syncthreads();
        }
    }
    gsync(ncta);

    // ======== P7: MLP1 GEMM (256 tiles, BN=128) ========
    for (int vb = rank; vb < MLP1_TILES; vb += ncta) {
        gemm_body<128, 2, 1, 0, 2, 32, 2>(
            vb % 16, vb / 16, 0,
            h1Hi, c1W, c1b, nullptr, m1Hi,
            C_, C_, C_, C4_, 0, 0, 0, 0, 0, 1.f, smem);
    }
    gsync(ncta);

    // ======== P8: MLP2 GEMM (128 tiles) ========
    for (int vb = rank; vb < MLP2_TILES; vb += ncta) {
        gemm_body<64, 0, 0, 0, 3, 64, 2>(
            vb % 8, vb / 8, 0,
            m1Hi, c2W, c2b, m2, nullptr,
            C4_, C4_, C4_, C_, 0, 0, 0, 0, 0, 1.f, smem);
    }
    gsync(ncta);

    // ======== P9: LN2 + output transpose (2048 rows) ========
    {
        __shared__ float sm2[16];
        for (int vb = rank; vb < LN_TILES; vb += ncta) {
            const int row = vb;
            const int l = row / B_, b = row % B_;
            size_t base = (size_t)row * C_;
            float v0 = m2[base + tid] + h1[base + tid];
            float v1 = m2[base + tid + 256] + h1[base + tid + 256];
            float s = warpSum(v0 + v1);
            float q = warpSum(v0 * v0 + v1 * v1);
            if (lane == 0) { sm2[w] = s; sm2[8 + w] = q; }
            __syncthreads();
            float S = 0.f, Q = 0.f;
#pragma unroll
            for (int i = 0; i < 8; i++) { S += sm2[i]; Q += sm2[8 + i]; }
            float mean = S * (1.f / C_);
            float var = Q * (1.f / C_) - mean * mean;
            float r = rsqrtf(var + 1e-5f);
            size_t ob = (size_t)b * CL_ + l;
            out[ob + (size_t)tid * L_]         = (v0 - mean) * r * ln2g[tid] + ln2b[tid];
            out[ob + (size_t)(tid + 256) * L_] = (v1 - mean) * r * ln2g[tid + 256] + ln2b[tid + 256];
            __syncthreads();
        }
    }
}

} // namespace

// ============================================================================
// Host launcher — ONE persistent kernel
// ============================================================================
extern "C" void kernel_launch(void* const* d_in, const int* in_sizes, int n_in,
                              void* d_out, int out_size)
{
    (void)in_sizes; (void)n_in; (void)out_size;

    const float* x       = (const float*)d_in[0];
    const float* theta_w = (const float*)d_in[1];
    const float* theta_b = (const float*)d_in[2];
    const float* phi_w   = (const float*)d_in[3];
    const float* phi_b   = (const float*)d_in[4];
    const float* g_w     = (const float*)d_in[5];
    const float* g_b     = (const float*)d_in[6];
    const float* wl_w    = (const float*)d_in[7];
    const float* wl_b    = (const float*)d_in[8];
    const float* wg_w    = (const float*)d_in[9];
    const float* wg_b    = (const float*)d_in[10];
    const float* conv1_w = (const float*)d_in[11];
    const float* conv1_b = (const float*)d_in[12];
    const float* conv2_w = (const float*)d_in[13];
    const float* conv2_b = (const float*)d_in[14];
    const float* ln1_g   = (const float*)d_in[15];
    const float* ln1_b   = (const float*)d_in[16];
    const float* ln2_g   = (const float*)d_in[17];
    const float* ln2_b   = (const float*)d_in[18];
    float* out = (float*)d_out;

    constexpr int SMEM = 82944;   // BN=64 KB=64 3-stage config (max over phases)
    cudaFuncSetAttribute(mega_kernel, cudaFuncAttributeMaxDynamicSharedMemorySize, SMEM);

    int smCount = 148, perSM = 2;
    cudaDeviceGetAttribute(&smCount, cudaDevAttrMultiProcessorCount, 0);
    cudaOccupancyMaxActiveBlocksPerMultiprocessor(&perSM, mega_kernel, 256, SMEM);
    if (perSM < 1) perSM = 1;
    const int ncta = smCount * perSM;   // co-resident by construction -> no deadlock

    mega_kernel<<<ncta, 256, SMEM>>>(
        x, theta_w, phi_w, g_w, wg_w, conv1_w, conv2_w, theta_b, phi_b, g_b,
        wl_w, wl_b, wg_b, conv1_b, conv2_b, ln1_g, ln1_b, ln2_g, ln2_b,
        out, ncta);
}

// round 15
// speedup vs baseline: 1.1911x; 1.1911x over previous
#include <cuda_runtime.h>
#include <cuda_fp16.h>
#include <math.h>
#include <stdint.h>

// ============================================================================
// Problem constants
// ============================================================================
namespace {
constexpr int B_ = 8, C_ = 512, L_ = 256;
constexpr int CL_ = C_ * L_;           // 131072
constexpr int C3_ = 3 * C_;            // 1536
constexpr int C4_ = 4 * C_;            // 2048
constexpr int NR_ = L_ * B_;           // 2048
constexpr size_t BLL_ = (size_t)B_ * L_ * L_;
constexpr float SCALE_ = 0.044194173824159216f; // 512^-0.5

// ---------------- scratch offsets (float units) ----------------
constexpr size_t OFF_XT_HI   = 0;                                    // f16 [B,L,C]
constexpr size_t OFF_XT32    = OFF_XT_HI   + (size_t)B_ * CL_ / 2;   // f32 [B,L,C]
constexpr size_t OFF_WQKV_HI = OFF_XT32    + (size_t)B_ * CL_;       // f16 [3C,C]
constexpr size_t OFF_QKV_B   = OFF_WQKV_HI + (size_t)C3_ * C_ / 2;   // f32 [1536]
constexpr size_t OFF_WWG_HI  = OFF_QKV_B   + 1536;
constexpr size_t OFF_C1WHI   = OFF_WWG_HI  + (size_t)C_ * C_ / 2;
constexpr size_t OFF_C2WHI   = OFF_C1WHI   + (size_t)C4_ * C_ / 2;
constexpr size_t OFF_QKVT_HI = OFF_C2WHI   + (size_t)C_ * C4_ / 2;   // f16 [B,L,3C]
constexpr size_t OFF_SG      = OFF_QKVT_HI + (size_t)B_ * L_ * C3_ / 2; // f16 [2][B,L,L]
constexpr size_t OFF_GP_HI   = OFF_SG      + BLL_;                   // f16 [B,L,L]
constexpr size_t OFF_GG2_HI  = OFF_GP_HI   + BLL_ / 2;               // f16 [B,C,L]
constexpr size_t OFF_GBAR    = OFF_GG2_HI  + (size_t)B_ * CL_ / 2;
constexpr size_t OFF_GATE    = OFF_GBAR    + (size_t)B_ * L_;
constexpr size_t OFF_GOUTT_HI= OFF_GATE    + (size_t)B_ * L_;        // f16 [B,L,C]
constexpr size_t OFF_GOUT2T  = OFF_GOUTT_HI+ (size_t)B_ * CL_ / 2;   // f32 [B,L,C]
constexpr size_t OFF_H1      = OFF_GOUT2T  + (size_t)B_ * CL_;       // f32 [NR,C]
constexpr size_t OFF_H1HI    = OFF_H1      + (size_t)NR_ * C_;       // f16 [NR,C]
constexpr size_t OFF_M1HI    = OFF_H1HI    + (size_t)NR_ * C_ / 2;   // f16 [NR,C4]
constexpr size_t OFF_M2      = OFF_M1HI    + (size_t)NR_ * C4_ / 2;  // f32 [NR,C]
constexpr size_t SCRATCH_TOTAL = OFF_M2    + (size_t)NR_ * C_;
} // namespace

__device__ __align__(256) float d_scratch[SCRATCH_TOTAL];

// ============================================================================
// PTX helpers — sm_80-era only (mma.sync / ldmatrix / cp.async).
// ============================================================================
__device__ __forceinline__ uint32_t smem_to_u32(const void* p) {
    uint32_t a;
    asm("{ .reg .u64 t; cvta.to.shared.u64 t, %1; cvt.u32.u64 %0, t; }" : "=r"(a) : "l"(p));
    return a;
}
__device__ __forceinline__ void ldmat4(uint32_t (&r)[4], uint32_t addr) {
    asm volatile("ldmatrix.sync.aligned.m8n8.x4.shared.b16 {%0,%1,%2,%3}, [%4];"
                 : "=r"(r[0]), "=r"(r[1]), "=r"(r[2]), "=r"(r[3]) : "r"(addr));
}
__device__ __forceinline__ void mma16816(float (&d)[4], const uint32_t (&a)[4], const uint32_t b0, const uint32_t b1) {
    asm volatile("mma.sync.aligned.m16n8k16.row.col.f32.f16.f16.f32 "
                 "{%0,%1,%2,%3}, {%4,%5,%6,%7}, {%8,%9}, {%0,%1,%2,%3};"
                 : "+f"(d[0]), "+f"(d[1]), "+f"(d[2]), "+f"(d[3])
                 : "r"(a[0]), "r"(a[1]), "r"(a[2]), "r"(a[3]), "r"(b0), "r"(b1));
}
__device__ __forceinline__ void cp16(uint32_t saddr, const void* g) {
    asm volatile("cp.async.cg.shared.global [%0], [%1], 16;" :: "r"(saddr), "l"(g));
}
#define CP_COMMIT() asm volatile("cp.async.commit_group;" ::: "memory")
template <int N>
__device__ __forceinline__ void cp_wait() {
    asm volatile("cp.async.wait_group %0;" :: "n"(N) : "memory");
}

namespace {

__device__ __forceinline__ float warpSum(float v) {
#pragma unroll
    for (int o = 16; o; o >>= 1) v += __shfl_xor_sync(0xffffffffu, v, o);
    return v;
}
__device__ __forceinline__ float warpMax(float v) {
#pragma unroll
    for (int o = 16; o; o >>= 1) v = fmaxf(v, __shfl_xor_sync(0xffffffffu, v, o));
    return v;
}
__device__ __forceinline__ float mishf(float v) {
    float sp = fmaxf(v, 0.f) + log1pf(__expf(-fabsf(v)));
    return v * tanhf(sp);
}

// ============================================================================
// fp16 tensor-core GEMM body. 1-pass plain fp16, NT layout:
//   A [M,K] K-contig (lda) ; B [N,K] K-contig (ldb). D = A·B^T (fp32 accum).
// v = scale*D (+ biasN); ACT=1 -> mish. OUTFMT 0: f32 ; 2: f16.
// FUSE=1: z encodes (sel = z>>3, b = z&7); B += sel*selB, out += sel*selO.
// WM = warps along M. 4 warps along N always.
// ============================================================================
template <int BN, int OUTFMT, int ACT, int FUSE, int STAGES, int KB, int WM>
__device__ __forceinline__ void gemm_body(
    const __half* __restrict__ A, const __half* __restrict__ Bm,
    const float* __restrict__ biasN,
    float* __restrict__ outF, __half* __restrict__ outH,
    int K, int lda, int ldb, int ldOut,
    size_t sA, size_t sB, size_t sO, size_t selB, size_t selO, float scale,
    char* smem)
{
    constexpr int BM = 128;
    constexpr int TPB = WM * 128;
    constexpr int MI = BM / (WM * 16);
    constexpr int SROW = KB * 2 + 16;
    constexpr int CHR = KB / 8;
    constexpr int ATILE = BM * SROW;
    constexpr int BTILE = BN * SROW;
    constexpr int STAGE = ATILE + BTILE;
    constexpr int WN = BN / 4;
    constexpr int NFRAG = WN / 8;
    constexpr int NKS = KB / 16;

    const uint32_t sb = smem_to_u32(smem);
    const int tid = threadIdx.x, lane = tid & 31, wid = tid >> 5;
    const int wm = wid & (WM - 1), wn = wid / WM;
    const int m0 = blockIdx.y * BM, n0 = blockIdx.x * BN;
    const int z = blockIdx.z;
    const int b = FUSE ? (z & 7) : z;
    const int sel = FUSE ? (z >> 3) : 0;

    A += (size_t)b * sA;
    Bm += (size_t)b * sB + (size_t)sel * selB;
    if (OUTFMT == 0) outF += (size_t)b * sO + (size_t)sel * selO;
    else             outH += (size_t)b * sO + (size_t)sel * selO;

    float acc[MI][NFRAG][4];
#pragma unroll
    for (int i = 0; i < MI; i++)
#pragma unroll
        for (int j = 0; j < NFRAG; j++)
#pragma unroll
            for (int q = 0; q < 4; q++) acc[i][j][q] = 0.f;

    auto load_stage = [&](int ch, int st) {
        const int k0 = ch * KB;
        const uint32_t base = sb + st * STAGE;
#pragma unroll
        for (int c = tid; c < BM * CHR; c += TPB) {
            int r = c / CHR, cc = c % CHR;
            cp16(base + r * SROW + cc * 16, A + (size_t)(m0 + r) * lda + k0 + cc * 8);
        }
#pragma unroll
        for (int c = tid; c < BN * CHR; c += TPB) {
            int r = c / CHR, cc = c % CHR;
            cp16(base + ATILE + r * SROW + cc * 16, Bm + (size_t)(n0 + r) * ldb + k0 + cc * 8);
        }
        CP_COMMIT();
    };

    const int nch = K / KB;
#pragma unroll
    for (int s = 0; s < STAGES - 1; s++) load_stage(s, s);

    int cs = 0;
    int ps = (STAGES - 1) % STAGES;
    for (int ch = 0; ch < nch; ch++) {
        cp_wait<STAGES - 2>();
        __syncthreads();
        const int pf = ch + STAGES - 1;
        if (pf < nch) load_stage(pf, ps);
        else CP_COMMIT();

        const uint32_t aBase = sb + cs * STAGE;
        const uint32_t bBase = aBase + ATILE;
#pragma unroll
        for (int ks = 0; ks < NKS; ks++) {
            const uint32_t colOff = (uint32_t)(ks * 2 + (lane >> 4)) * 16;
            uint32_t a_f[MI][4];
#pragma unroll
            for (int mi = 0; mi < MI; mi++) {
                uint32_t addr = aBase + (uint32_t)(wm * (MI * 16) + mi * 16 + (lane & 15)) * SROW + colOff;
                ldmat4(a_f[mi], addr);
            }
#pragma unroll
            for (int nt = 0; nt < NFRAG / 2; nt++) {
                uint32_t addr = bBase + (uint32_t)(wn * WN + nt * 16 + (lane & 15)) * SROW + colOff;
                uint32_t bf[4];
                ldmat4(bf, addr);
#pragma unroll
                for (int half = 0; half < 2; half++) {
                    const int ni = nt * 2 + half;
#pragma unroll
                    for (int mi = 0; mi < MI; mi++)
                        mma16816(acc[mi][ni], a_f[mi], bf[half], bf[2 + half]);
                }
            }
        }
        cs = (cs + 1 == STAGES) ? 0 : cs + 1;
        ps = (ps + 1 == STAGES) ? 0 : ps + 1;
    }

    // ---------------- epilogue ----------------
    const int g = lane >> 2, tg = lane & 3;
#pragma unroll
    for (int mi = 0; mi < MI; mi++) {
#pragma unroll
        for (int ni = 0; ni < NFRAG; ni++) {
            const int col = n0 + wn * WN + ni * 8 + tg * 2;
            const float b0 = biasN ? biasN[col] : 0.f;
            const float b1 = biasN ? biasN[col + 1] : 0.f;
#pragma unroll
            for (int h = 0; h < 2; h++) {
                const int row = m0 + wm * (MI * 16) + mi * 16 + g + h * 8;
                float v0 = acc[mi][ni][h * 2 + 0] * scale + b0;
                float v1 = acc[mi][ni][h * 2 + 1] * scale + b1;
                if (ACT == 1) { v0 = mishf(v0); v1 = mishf(v1); }
                const size_t o = (size_t)row * ldOut + col;
                if (OUTFMT == 0) {
                    float2 fp; fp.x = v0; fp.y = v1;
                    *(float2*)(outF + o) = fp;
                } else {
                    __half2 hp;
                    hp.x = __float2half_rn(v0);
                    hp.y = __float2half_rn(v1);
                    *(__half2*)(outH + o) = hp;
                }
            }
        }
    }
}

template <int BN, int OUTFMT, int ACT, int FUSE, int STAGES, int KB, int WM>
__global__ void __launch_bounds__(WM * 128) gemm_mma(
    const __half* __restrict__ A, const __half* __restrict__ Bm,
    const float* __restrict__ biasN,
    float* __restrict__ outF, __half* __restrict__ outH,
    int K, int lda, int ldb, int ldOut,
    size_t sA, size_t sB, size_t sO, size_t selB, size_t selO, float scale)
{
    extern __shared__ char smem[];
    gemm_body<BN, OUTFMT, ACT, FUSE, STAGES, KB, WM>(
        A, Bm, biasN, outF, outH,
        K, lda, ldb, ldOut, sA, sB, sO, selB, selO, scale, smem);
}

// ============================================================================
// Fused Sg/Sl GEMM (z<16, f16 scores out) + g-transpose/gbar (z>=16).
// Grid (4, 2, 24), 256 threads.
// ============================================================================
__global__ void __launch_bounds__(256) sgsl_gtrans(
    const __half* __restrict__ qkvHi,
    __half* __restrict__ SgH,
    __half* __restrict__ gg2Hi,
    float* __restrict__ gbar)
{
    extern __shared__ char smem[];
    if (blockIdx.z < 16) {
        gemm_body<64, 2, 0, 1, 3, 64, 2>(
            qkvHi + C_, qkvHi, nullptr, nullptr, SgH,
            C_, C3_, C3_, L_, (size_t)L_ * C3_, (size_t)L_ * C3_, (size_t)L_ * L_,
            (size_t)(2 * C_), BLL_, SCALE_, smem);
        return;
    }
    // ---- transpose + gbar path (256 threads, 8 warps) ----
    __half (*th)[34] = (__half(*)[34])smem;
    const int vb = (blockIdx.z - 16) * 8 + blockIdx.y * 4 + blockIdx.x;
    const int b = vb >> 3;
    const int l0 = (vb & 7) * 32;
    const int tx = threadIdx.x & 31, ty = threadIdx.x >> 5;

    for (int ct = 0; ct < 16; ct++) {
        const int c0 = ct * 32;
#pragma unroll
        for (int j = 0; j < 4; j++) {
            size_t idx = ((size_t)b * L_ + l0 + ty + j * 8) * C3_ + 2 * C_ + c0 + tx;
            th[ty + j * 8][tx] = qkvHi[idx];
        }
        __syncthreads();
#pragma unroll
        for (int j = 0; j < 4; j++) {
            int c = c0 + ty + j * 8;
            size_t o = ((size_t)b * C_ + c) * L_ + l0 + tx;
            gg2Hi[o] = th[tx][ty + j * 8];
        }
        __syncthreads();
    }
#pragma unroll
    for (int i = 0; i < 4; i++) {
        const int l = l0 + ty * 4 + i;
        const size_t base = ((size_t)b * L_ + l) * C3_ + 2 * C_;
        float s = 0.f;
#pragma unroll
        for (int c = tx; c < C_; c += 32)
            s += __half2float(qkvHi[base + c]);
        s = warpSum(s);
        if (tx == 0) gbar[b * L_ + l] = s * (1.f / C_);
    }
}

// ============================================================================
// prep_all: ONE launch = fp16 weight conversion (8/thread) + bias + x transpose
// ============================================================================
constexpr int PREP_WELEMS = 3 * C_ * C_ + C_ * C_ + C4_ * C_ + C_ * C4_;
constexpr int PREP_NW8 = PREP_WELEMS / 8 / 256;       // 1536
constexpr int PREP_NB = 6;
constexpr int PREP_NT = (L_ / 32) * (C_ / 32) * B_;   // 1024

__global__ void prep_all(const float* __restrict__ x,
                         const float* __restrict__ tw, const float* __restrict__ pw,
                         const float* __restrict__ gw, const float* __restrict__ wgw,
                         const float* __restrict__ c1w, const float* __restrict__ c2w,
                         const float* __restrict__ tb, const float* __restrict__ pb,
                         const float* __restrict__ gb,
                         __half* __restrict__ qkvW, __half* __restrict__ wgW,
                         __half* __restrict__ c1W, __half* __restrict__ c2W,
                         float* __restrict__ qkvb,
                         __half* __restrict__ xtHi, float* __restrict__ xt32)
{
    __shared__ float t[32][33];
    const int bid = blockIdx.x;
    if (bid < PREP_NW8) {
        constexpr int NW = C_ * C_;
        constexpr int N1 = 3 * NW;
        constexpr int N2 = N1 + NW;
        constexpr int N3 = N2 + C4_ * C_;
        const int i = (bid * 256 + threadIdx.x) * 8;
        const float* src;
        __half* dst;
        int j;
        if (i < N1) {
            j = i & (NW - 1);
            src = (i < NW) ? tw : (i < 2 * NW ? pw : gw);
            dst = qkvW + i;
        } else if (i < N2) { j = i - N1; src = wgw; dst = wgW + j; }
        else if (i < N3)   { j = i - N2; src = c1w; dst = c1W + j; }
        else               { j = i - N3; src = c2w; dst = c2W + j; }
        float4 va = *(const float4*)(src + j);
        float4 vb = *(const float4*)(src + j + 4);
        __half2 h[4];
        h[0].x = __float2half_rn(va.x); h[0].y = __float2half_rn(va.y);
        h[1].x = __float2half_rn(va.z); h[1].y = __float2half_rn(va.w);
        h[2].x = __float2half_rn(vb.x); h[2].y = __float2half_rn(vb.y);
        h[3].x = __float2half_rn(vb.z); h[3].y = __float2half_rn(vb.w);
        *(uint4*)dst = *(uint4*)h;
    } else if (bid < PREP_NW8 + PREP_NB) {
        const int j = (bid - PREP_NW8) * 256 + threadIdx.x;
        if (j < C3_)
            qkvb[j] = (j < C_) ? tb[j] : (j < 2 * C_ ? pb[j - C_] : gb[j - 2 * C_]);
    } else {
        const int tI = bid - PREP_NW8 - PREP_NB;
        const int b = tI >> 7;
        const int rem = tI & 127;
        const int c0 = (rem & 15) * 32;
        const int l0 = (rem >> 4) * 32;
        const int tx = threadIdx.x & 31, ty = threadIdx.x >> 5;
        const float* xb = x + (size_t)b * CL_;
#pragma unroll
        for (int j = 0; j < 4; j++)
            t[ty + j * 8][tx] = xb[(size_t)(c0 + ty + j * 8) * L_ + l0 + tx];
        __syncthreads();
#pragma unroll
        for (int j = 0; j < 4; j++) {
            int l = l0 + ty + j * 8;
            float v = t[tx][ty + j * 8];
            size_t o = ((size_t)b * L_ + l) * C_ + c0 + tx;
            xtHi[o] = __float2half_rn(v);
            xt32[o] = v;
        }
    }
}

// ============================================================================
// softmax_gate: warp-per-row, f16 scores in. grid (L/8, B), 256 threads.
// ============================================================================
__global__ void __launch_bounds__(256) softmax_gate(
    const __half* __restrict__ Sg,
    const __half* __restrict__ Sl,
    const float* __restrict__ gbar,
    const float* __restrict__ wlw,
    const float* __restrict__ wlb,
    __half* __restrict__ pHi,
    float* __restrict__ gate)
{
    const int w = threadIdx.x >> 5, lane = threadIdx.x & 31;
    const int l = blockIdx.x * 8 + w;
    const int b = blockIdx.y;
    const size_t row = (size_t)b * L_ + l;

    // --- softmax over 256 f16 elems: 8 per lane (one uint4) ---
    uint4 raw = *(const uint4*)(Sg + row * L_ + lane * 8);
    __half2* rh = (__half2*)&raw;
    float v[8];
#pragma unroll
    for (int i = 0; i < 4; i++) {
        float2 f = __half22float2(rh[i]);
        v[2 * i] = f.x; v[2 * i + 1] = f.y;
    }
    float mx = v[0];
#pragma unroll
    for (int i = 1; i < 8; i++) mx = fmaxf(mx, v[i]);
    mx = warpMax(mx);
    float sum = 0.f;
#pragma unroll
    for (int i = 0; i < 8; i++) { v[i] = __expf(v[i] - mx); sum += v[i]; }
    sum = warpSum(sum);
    const float inv = 1.f / sum;
    __half2 hp[4];
#pragma unroll
    for (int i = 0; i < 4; i++) {
        hp[i].x = __float2half_rn(v[2 * i] * inv);
        hp[i].y = __float2half_rn(v[2 * i + 1] * inv);
    }
    *(uint4*)(pHi + row * L_ + lane * 8) = *(uint4*)hp;

    // --- banded local gate (zeros participate in softmax) ---
    const __half* slrow = Sl + row * L_;
    const float* gb = gbar + (size_t)b * L_;
    int m0 = l + lane - 32;
    int m1 = l + lane;
    bool v0 = (m0 >= 0) && (m0 < L_);
    bool v1 = (m1 >= 0) && (m1 < L_);
    float s0 = v0 ? __half2float(slrow[m0]) : 0.f;
    float s1 = v1 ? __half2float(slrow[m1]) : 0.f;
    float g0 = v0 ? gb[m0] : 0.f;
    float g1 = v1 ? gb[m1] : 0.f;
    float bx = warpMax(fmaxf(s0, s1));
    float e0 = __expf(s0 - bx), e1 = __expf(s1 - bx);
    float num = warpSum(e0 * g0 + e1 * g1);
    float den = warpSum(e0 + e1);
    if (lane == 0) {
        float pooled = num / den;
        float z = wlw[0] * pooled + wlb[0];
        gate[b * L_ + l] = 1.f / (1.f + __expf(-z));
    }
}

// ============================================================================
// LN1: h = gout2T*gate + xT32 ; h1 f32 + f16 at row (l*B+b), [*,C]
// ============================================================================
__global__ void ln1_kernel(const float* __restrict__ gout2T,
                           const float* __restrict__ gate,
                           const float* __restrict__ xt32,
                           const float* __restrict__ g1, const float* __restrict__ b1,
                           float* __restrict__ h1,
                           __half* __restrict__ h1hi)
{
    __shared__ float sm[16];
    int l = blockIdx.x, b = blockIdx.y, tid = threadIdx.x;
    int lane = tid & 31, w = tid >> 5;
    float gt = gate[b * L_ + l];
    size_t gbase = ((size_t)b * L_ + l) * C_;
    float v0 = fmaf(gout2T[gbase + tid], gt, xt32[gbase + tid]);
    float v1 = fmaf(gout2T[gbase + tid + 256], gt, xt32[gbase + tid + 256]);
    float s = warpSum(v0 + v1);
    float q = warpSum(v0 * v0 + v1 * v1);
    if (lane == 0) { sm[w] = s; sm[8 + w] = q; }
    __syncthreads();
    float S = 0.f, Q = 0.f;
#pragma unroll
    for (int i = 0; i < 8; i++) { S += sm[i]; Q += sm[8 + i]; }
    float mean = S * (1.f / C_);
    float var = Q * (1.f / C_) - mean * mean;
    float r = rsqrtf(var + 1e-5f);
    size_t o = ((size_t)l * B_ + b) * C_;
    float y0 = (v0 - mean) * r * g1[tid] + b1[tid];
    float y1 = (v1 - mean) * r * g1[tid + 256] + b1[tid + 256];
    h1[o + tid] = y0;
    h1[o + tid + 256] = y1;
    h1hi[o + tid] = __float2half_rn(y0);
    h1hi[o + tid + 256] = __float2half_rn(y1);
}

// ============================================================================
// LN2 v2: coalesced output. grid (L/32, B), 256 threads.
// Block handles 32 l's of batch b: per-row stats (warp-per-4-rows), then
// 16 c-tiles through a 32x33 SMEM transpose so out[b,c,l] stores are
// contiguous in l.
// ============================================================================
__global__ void __launch_bounds__(256) ln2_kernel(
    const float* __restrict__ m2,
    const float* __restrict__ h1,
    const float* __restrict__ g2, const float* __restrict__ b2,
    float* __restrict__ out)
{
    __shared__ float mean_s[32], inv_s[32];
    __shared__ float th[32][33];
    const int b = blockIdx.y;
    const int l0 = blockIdx.x * 32;
    const int lane = threadIdx.x & 31, w = threadIdx.x >> 5;

    // stats: warp w handles rows l0 + w*4 + i
#pragma unroll
    for (int i = 0; i < 4; i++) {
        const int lr = w * 4 + i;
        const size_t base = (size_t)((l0 + lr) * B_ + b) * C_;
        float s = 0.f, q = 0.f;
#pragma unroll 4
        for (int c = lane; c < C_; c += 32) {
            float v = m2[base + c] + h1[base + c];
            s += v; q += v * v;
        }
        s = warpSum(s); q = warpSum(q);
        if (lane == 0) {
            float mean = s * (1.f / C_);
            float var = q * (1.f / C_) - mean * mean;
            mean_s[lr] = mean;
            inv_s[lr] = rsqrtf(var + 1e-5f);
        }
    }
    __syncthreads();

    // apply + transpose stores
    for (int ct = 0; ct < 16; ct++) {
        const int c0 = ct * 32;
#pragma unroll
        for (int j = 0; j < 4; j++) {
            const int lr = w + j * 8;
            const size_t base = (size_t)((l0 + lr) * B_ + b) * C_ + c0 + lane;
            float v = m2[base] + h1[base];
            th[lr][lane] = (v - mean_s[lr]) * inv_s[lr] * g2[c0 + lane] + b2[c0 + lane];
        }
        __syncthreads();
#pragma unroll
        for (int j = 0; j < 4; j++) {
            const int cr = w + j * 8;
            out[((size_t)b * C_ + c0 + cr) * L_ + l0 + lane] = th[lane][cr];
        }
        __syncthreads();
    }
}

} // namespace

// ============================================================================
// Host launcher
// ============================================================================
extern "C" void kernel_launch(void* const* d_in, const int* in_sizes, int n_in,
                              void* d_out, int out_size)
{
    (void)in_sizes; (void)n_in; (void)out_size;
    float* scratch = nullptr;
    cudaGetSymbolAddress((void**)&scratch, d_scratch);

    const float* x       = (const float*)d_in[0];
    const float* theta_w = (const float*)d_in[1];
    const float* theta_b = (const float*)d_in[2];
    const float* phi_w   = (const float*)d_in[3];
    const float* phi_b   = (const float*)d_in[4];
    const float* g_w     = (const float*)d_in[5];
    const float* g_b     = (const float*)d_in[6];
    const float* wl_w    = (const float*)d_in[7];
    const float* wl_b    = (const float*)d_in[8];
    const float* wg_w    = (const float*)d_in[9];
    const float* wg_b    = (const float*)d_in[10];
    const float* conv1_w = (const float*)d_in[11];
    const float* conv1_b = (const float*)d_in[12];
    const float* conv2_w = (const float*)d_in[13];
    const float* conv2_b = (const float*)d_in[14];
    const float* ln1_g   = (const float*)d_in[15];
    const float* ln1_b   = (const float*)d_in[16];
    const float* ln2_g   = (const float*)d_in[17];
    const float* ln2_b   = (const float*)d_in[18];
    float* out = (float*)d_out;

    __half* xtHi   = (__half*)(scratch + OFF_XT_HI);
    float* xt32    = scratch + OFF_XT32;
    __half* wqkvW  = (__half*)(scratch + OFF_WQKV_HI);
    float* qkv_b   = scratch + OFF_QKV_B;
    __half* wwgW   = (__half*)(scratch + OFF_WWG_HI);
    __half* c1W    = (__half*)(scratch + OFF_C1WHI);
    __half* c2W    = (__half*)(scratch + OFF_C2WHI);
    __half* qkvHi  = (__half*)(scratch + OFF_QKVT_HI);
    __half* SgH    = (__half*)(scratch + OFF_SG);
    __half* gpHi   = (__half*)(scratch + OFF_GP_HI);
    __half* gg2Hi  = (__half*)(scratch + OFF_GG2_HI);
    float* gbar    = scratch + OFF_GBAR;
    float* gate    = scratch + OFF_GATE;
    __half* goHi   = (__half*)(scratch + OFF_GOUTT_HI);
    float* gout2T  = scratch + OFF_GOUT2T;
    float* h1      = scratch + OFF_H1;
    __half* h1Hi   = (__half*)(scratch + OFF_H1HI);
    __half* m1Hi   = (__half*)(scratch + OFF_M1HI);
    float* m2      = scratch + OFF_M2;

    // SMEM: BN=64 KB=64 3st: 82944 (2 CTA/SM) ; BN=128 KB=32 2st: 40960
    constexpr int SM_64  = 82944;
    constexpr int SM_128 = 40960;
    cudaFuncSetAttribute(sgsl_gtrans,                      cudaFuncAttributeMaxDynamicSharedMemorySize, SM_64);
    cudaFuncSetAttribute(gemm_mma<64, 2, 0, 0, 3, 64, 2>,  cudaFuncAttributeMaxDynamicSharedMemorySize, SM_64);
    cudaFuncSetAttribute(gemm_mma<64, 0, 0, 0, 3, 64, 2>,  cudaFuncAttributeMaxDynamicSharedMemorySize, SM_64);
    cudaFuncSetAttribute(gemm_mma<128, 2, 0, 0, 2, 32, 2>, cudaFuncAttributeMaxDynamicSharedMemorySize, SM_128);
    cudaFuncSetAttribute(gemm_mma<128, 2, 1, 0, 2, 32, 2>, cudaFuncAttributeMaxDynamicSharedMemorySize, SM_128);

    // 0) prep
    prep_all<<<PREP_NW8 + PREP_NB + PREP_NT, 256>>>(
        x, theta_w, phi_w, g_w, wg_w, conv1_w, conv2_w, theta_b, phi_b, g_b,
        wqkvW, wwgW, c1W, c2W, qkv_b, xtHi, xt32);

    // 1) fused qkv -> f16
    {
        dim3 grid(C3_ / 128, L_ / 128, B_);
        gemm_mma<128, 2, 0, 0, 2, 32, 2><<<grid, 256, SM_128>>>(
            xtHi, wqkvW, qkv_b, nullptr, qkvHi,
            C_, C_, C_, C3_, (size_t)L_ * C_, 0, (size_t)L_ * C3_, 0, 0, 1.f);
    }

    // 2) Sg & Sl (f16 scores) + g-transpose + gbar, ONE launch
    {
        dim3 grid(L_ / 64, L_ / 128, 16 + 8);
        sgsl_gtrans<<<grid, 256, SM_64>>>(qkvHi, SgH, gg2Hi, gbar);
    }

    // 3) fused softmax + local gate (warp-per-row, f16 in)
    softmax_gate<<<dim3(L_ / 8, B_), 256>>>(SgH, SgH + BLL_, gbar,
                                            wl_w, wl_b, gpHi, gate);

    // 4) goutT = gp @ gg2^T -> f16 ; gout2T = goutT @ wg^T + wg_b -> f32
    {
        dim3 grid(C_ / 64, L_ / 128, B_);
        gemm_mma<64, 2, 0, 0, 3, 64, 2><<<grid, 256, SM_64>>>(
            gpHi, gg2Hi, nullptr, nullptr, goHi,
            L_, L_, L_, C_, (size_t)L_ * L_, (size_t)CL_, (size_t)L_ * C_, 0, 0, 1.f);
        gemm_mma<64, 0, 0, 0, 3, 64, 2><<<grid, 256, SM_64>>>(
            goHi, wwgW, wg_b, gout2T, nullptr,
            C_, C_, C_, C_, (size_t)L_ * C_, 0, (size_t)L_ * C_, 0, 0, 1.f);
    }

    // 5) LN1 -> h1 (f32 + f16)
    ln1_kernel<<<dim3(L_, B_), 256>>>(gout2T, gate, xt32, ln1_g, ln1_b, h1, h1Hi);

    // 6) MLP1: m1 = Mish(h1 @ conv1^T + b) -> f16
    {
        dim3 grid(C4_ / 128, NR_ / 128, 1);
        gemm_mma<128, 2, 1, 0, 2, 32, 2><<<grid, 256, SM_128>>>(
            h1Hi, c1W, conv1_b, nullptr, m1Hi,
            C_, C_, C_, C4_, 0, 0, 0, 0, 0, 1.f);
    }

    // 7) MLP2: m2 = m1 @ conv2^T + b -> f32
    {
        dim3 grid(C_ / 64, NR_ / 128, 1);
        gemm_mma<64, 0, 0, 0, 3, 64, 2><<<grid, 256, SM_64>>>(
            m1Hi, c2W, conv2_b, m2, nullptr,
            C4_, C4_, C4_, C_, 0, 0, 0, 0, 0, 1.f);
    }

    // 8) LN2 + coalesced transpose out
    ln2_kernel<<<dim3(L_ / 32, B_), 256>>>(m2, h1, ln2_g, ln2_b, out);
}

// round 16
// speedup vs baseline: 1.2824x; 1.0767x over previous
#include <cuda_runtime.h>
#include <cuda_fp16.h>
#include <math.h>
#include <stdint.h>

// ============================================================================
// Problem constants
// ============================================================================
namespace {
constexpr int B_ = 8, C_ = 512, L_ = 256;
constexpr int CL_ = C_ * L_;           // 131072
constexpr int C3_ = 3 * C_;            // 1536
constexpr int C4_ = 4 * C_;            // 2048
constexpr int NR_ = L_ * B_;           // 2048
constexpr size_t BLL_ = (size_t)B_ * L_ * L_;
constexpr float SCALE_ = 0.044194173824159216f; // 512^-0.5

// ---------------- scratch offsets (float units) ----------------
constexpr size_t OFF_XT_HI   = 0;                                    // f16 [B,L,C]
constexpr size_t OFF_XT32    = OFF_XT_HI   + (size_t)B_ * CL_ / 2;   // f32 [B,L,C]
constexpr size_t OFF_WQKV_HI = OFF_XT32    + (size_t)B_ * CL_;       // f16 [3C,C]
constexpr size_t OFF_QKV_B   = OFF_WQKV_HI + (size_t)C3_ * C_ / 2;   // f32 [1536]
constexpr size_t OFF_WWG_HI  = OFF_QKV_B   + 1536;
constexpr size_t OFF_C1WHI   = OFF_WWG_HI  + (size_t)C_ * C_ / 2;
constexpr size_t OFF_C2WHI   = OFF_C1WHI   + (size_t)C4_ * C_ / 2;
constexpr size_t OFF_QKVT_HI = OFF_C2WHI   + (size_t)C_ * C4_ / 2;   // f16 [B,L,3C]
constexpr size_t OFF_SG      = OFF_QKVT_HI + (size_t)B_ * L_ * C3_ / 2; // f16 [2][B,L,L]
constexpr size_t OFF_GP_HI   = OFF_SG      + BLL_;                   // f16 [B,L,L]
constexpr size_t OFF_GG2_HI  = OFF_GP_HI   + BLL_ / 2;               // f16 [B,C,L]
constexpr size_t OFF_GBAR    = OFF_GG2_HI  + (size_t)B_ * CL_ / 2;
constexpr size_t OFF_GATE    = OFF_GBAR    + (size_t)B_ * L_;
constexpr size_t OFF_GOUTT_HI= OFF_GATE    + (size_t)B_ * L_;        // f16 [B,L,C]
constexpr size_t OFF_GOUT2T  = OFF_GOUTT_HI+ (size_t)B_ * CL_ / 2;   // f32 [B,L,C]
constexpr size_t OFF_H1      = OFF_GOUT2T  + (size_t)B_ * CL_;       // f32 [NR,C]
constexpr size_t OFF_H1HI    = OFF_H1      + (size_t)NR_ * C_;       // f16 [NR,C]
constexpr size_t OFF_M1HI    = OFF_H1HI    + (size_t)NR_ * C_ / 2;   // f16 [NR,C4]
constexpr size_t OFF_M2      = OFF_M1HI    + (size_t)NR_ * C4_ / 2;  // f32 [NR,C]
constexpr size_t SCRATCH_TOTAL = OFF_M2    + (size_t)NR_ * C_;
} // namespace

__device__ __align__(256) float d_scratch[SCRATCH_TOTAL];

// ============================================================================
// PTX helpers — sm_80-era only (mma.sync / ldmatrix / cp.async).
// ============================================================================
__device__ __forceinline__ uint32_t smem_to_u32(const void* p) {
    uint32_t a;
    asm("{ .reg .u64 t; cvta.to.shared.u64 t, %1; cvt.u32.u64 %0, t; }" : "=r"(a) : "l"(p));
    return a;
}
__device__ __forceinline__ void ldmat4(uint32_t (&r)[4], uint32_t addr) {
    asm volatile("ldmatrix.sync.aligned.m8n8.x4.shared.b16 {%0,%1,%2,%3}, [%4];"
                 : "=r"(r[0]), "=r"(r[1]), "=r"(r[2]), "=r"(r[3]) : "r"(addr));
}
__device__ __forceinline__ void mma16816(float (&d)[4], const uint32_t (&a)[4], const uint32_t b0, const uint32_t b1) {
    asm volatile("mma.sync.aligned.m16n8k16.row.col.f32.f16.f16.f32 "
                 "{%0,%1,%2,%3}, {%4,%5,%6,%7}, {%8,%9}, {%0,%1,%2,%3};"
                 : "+f"(d[0]), "+f"(d[1]), "+f"(d[2]), "+f"(d[3])
                 : "r"(a[0]), "r"(a[1]), "r"(a[2]), "r"(a[3]), "r"(b0), "r"(b1));
}
__device__ __forceinline__ void cp16(uint32_t saddr, const void* g) {
    asm volatile("cp.async.cg.shared.global [%0], [%1], 16;" :: "r"(saddr), "l"(g));
}
#define CP_COMMIT() asm volatile("cp.async.commit_group;" ::: "memory")
template <int N>
__device__ __forceinline__ void cp_wait() {
    asm volatile("cp.async.wait_group %0;" :: "n"(N) : "memory");
}

namespace {

__device__ __forceinline__ float warpSum(float v) {
#pragma unroll
    for (int o = 16; o; o >>= 1) v += __shfl_xor_sync(0xffffffffu, v, o);
    return v;
}
__device__ __forceinline__ float warpMax(float v) {
#pragma unroll
    for (int o = 16; o; o >>= 1) v = fmaxf(v, __shfl_xor_sync(0xffffffffu, v, o));
    return v;
}
__device__ __forceinline__ float mishf(float v) {
    float sp = fmaxf(v, 0.f) + log1pf(__expf(-fabsf(v)));
    return v * tanhf(sp);
}

// ============================================================================
// fp16 tensor-core GEMM body. 1-pass plain fp16, NT layout:
//   A [M,K] K-contig (lda) ; B [N,K] K-contig (ldb). D = A·B^T (fp32 accum).
// v = scale*D (+ biasN); ACT=1 -> mish. OUTFMT 0: f32 ; 2: f16.
// FUSE=1: z encodes (sel = z>>3, b = z&7); B += sel*selB, out += sel*selO.
// WM = warps along M. 4 warps along N always.
// ============================================================================
template <int BN, int OUTFMT, int ACT, int FUSE, int STAGES, int KB, int WM>
__device__ __forceinline__ void gemm_body(
    const __half* __restrict__ A, const __half* __restrict__ Bm,
    const float* __restrict__ biasN,
    float* __restrict__ outF, __half* __restrict__ outH,
    int K, int lda, int ldb, int ldOut,
    size_t sA, size_t sB, size_t sO, size_t selB, size_t selO, float scale,
    char* smem)
{
    constexpr int BM = 128;
    constexpr int TPB = WM * 128;
    constexpr int MI = BM / (WM * 16);
    constexpr int SROW = KB * 2 + 16;
    constexpr int CHR = KB / 8;
    constexpr int ATILE = BM * SROW;
    constexpr int BTILE = BN * SROW;
    constexpr int STAGE = ATILE + BTILE;
    constexpr int WN = BN / 4;
    constexpr int NFRAG = WN / 8;
    constexpr int NKS = KB / 16;

    const uint32_t sb = smem_to_u32(smem);
    const int tid = threadIdx.x, lane = tid & 31, wid = tid >> 5;
    const int wm = wid & (WM - 1), wn = wid / WM;
    const int m0 = blockIdx.y * BM, n0 = blockIdx.x * BN;
    const int z = blockIdx.z;
    const int b = FUSE ? (z & 7) : z;
    const int sel = FUSE ? (z >> 3) : 0;

    A += (size_t)b * sA;
    Bm += (size_t)b * sB + (size_t)sel * selB;
    if (OUTFMT == 0) outF += (size_t)b * sO + (size_t)sel * selO;
    else             outH += (size_t)b * sO + (size_t)sel * selO;

    float acc[MI][NFRAG][4];
#pragma unroll
    for (int i = 0; i < MI; i++)
#pragma unroll
        for (int j = 0; j < NFRAG; j++)
#pragma unroll
            for (int q = 0; q < 4; q++) acc[i][j][q] = 0.f;

    auto load_stage = [&](int ch, int st) {
        const int k0 = ch * KB;
        const uint32_t base = sb + st * STAGE;
#pragma unroll
        for (int c = tid; c < BM * CHR; c += TPB) {
            int r = c / CHR, cc = c % CHR;
            cp16(base + r * SROW + cc * 16, A + (size_t)(m0 + r) * lda + k0 + cc * 8);
        }
#pragma unroll
        for (int c = tid; c < BN * CHR; c += TPB) {
            int r = c / CHR, cc = c % CHR;
            cp16(base + ATILE + r * SROW + cc * 16, Bm + (size_t)(n0 + r) * ldb + k0 + cc * 8);
        }
        CP_COMMIT();
    };

    const int nch = K / KB;
#pragma unroll
    for (int s = 0; s < STAGES - 1; s++) load_stage(s, s);

    int cs = 0;
    int ps = (STAGES - 1) % STAGES;
    for (int ch = 0; ch < nch; ch++) {
        cp_wait<STAGES - 2>();
        __syncthreads();
        const int pf = ch + STAGES - 1;
        if (pf < nch) load_stage(pf, ps);
        else CP_COMMIT();

        const uint32_t aBase = sb + cs * STAGE;
        const uint32_t bBase = aBase + ATILE;
#pragma unroll
        for (int ks = 0; ks < NKS; ks++) {
            const uint32_t colOff = (uint32_t)(ks * 2 + (lane >> 4)) * 16;
            uint32_t a_f[MI][4];
#pragma unroll
            for (int mi = 0; mi < MI; mi++) {
                uint32_t addr = aBase + (uint32_t)(wm * (MI * 16) + mi * 16 + (lane & 15)) * SROW + colOff;
                ldmat4(a_f[mi], addr);
            }
#pragma unroll
            for (int nt = 0; nt < NFRAG / 2; nt++) {
                uint32_t addr = bBase + (uint32_t)(wn * WN + nt * 16 + (lane & 15)) * SROW + colOff;
                uint32_t bf[4];
                ldmat4(bf, addr);
#pragma unroll
                for (int half = 0; half < 2; half++) {
                    const int ni = nt * 2 + half;
#pragma unroll
                    for (int mi = 0; mi < MI; mi++)
                        mma16816(acc[mi][ni], a_f[mi], bf[half], bf[2 + half]);
                }
            }
        }
        cs = (cs + 1 == STAGES) ? 0 : cs + 1;
        ps = (ps + 1 == STAGES) ? 0 : ps + 1;
    }

    // ---------------- epilogue ----------------
    const int g = lane >> 2, tg = lane & 3;
#pragma unroll
    for (int mi = 0; mi < MI; mi++) {
#pragma unroll
        for (int ni = 0; ni < NFRAG; ni++) {
            const int col = n0 + wn * WN + ni * 8 + tg * 2;
            const float b0 = biasN ? biasN[col] : 0.f;
            const float b1 = biasN ? biasN[col + 1] : 0.f;
#pragma unroll
            for (int h = 0; h < 2; h++) {
                const int row = m0 + wm * (MI * 16) + mi * 16 + g + h * 8;
                float v0 = acc[mi][ni][h * 2 + 0] * scale + b0;
                float v1 = acc[mi][ni][h * 2 + 1] * scale + b1;
                if (ACT == 1) { v0 = mishf(v0); v1 = mishf(v1); }
                const size_t o = (size_t)row * ldOut + col;
                if (OUTFMT == 0) {
                    float2 fp; fp.x = v0; fp.y = v1;
                    *(float2*)(outF + o) = fp;
                } else {
                    __half2 hp;
                    hp.x = __float2half_rn(v0);
                    hp.y = __float2half_rn(v1);
                    *(__half2*)(outH + o) = hp;
                }
            }
        }
    }
}

template <int BN, int OUTFMT, int ACT, int FUSE, int STAGES, int KB, int WM>
__global__ void __launch_bounds__(WM * 128) gemm_mma(
    const __half* __restrict__ A, const __half* __restrict__ Bm,
    const float* __restrict__ biasN,
    float* __restrict__ outF, __half* __restrict__ outH,
    int K, int lda, int ldb, int ldOut,
    size_t sA, size_t sB, size_t sO, size_t selB, size_t selO, float scale)
{
    extern __shared__ char smem[];
    gemm_body<BN, OUTFMT, ACT, FUSE, STAGES, KB, WM>(
        A, Bm, biasN, outF, outH,
        K, lda, ldb, ldOut, sA, sB, sO, selB, selO, scale, smem);
}

// ============================================================================
// Fused Sg/Sl GEMM (z<16, f16 scores out) + g-transpose/gbar (z>=16).
// Grid (4, 2, 24), 256 threads.
// ============================================================================
__global__ void __launch_bounds__(256) sgsl_gtrans(
    const __half* __restrict__ qkvHi,
    __half* __restrict__ SgH,
    __half* __restrict__ gg2Hi,
    float* __restrict__ gbar)
{
    extern __shared__ char smem[];
    if (blockIdx.z < 16) {
        gemm_body<64, 2, 0, 1, 3, 64, 2>(
            qkvHi + C_, qkvHi, nullptr, nullptr, SgH,
            C_, C3_, C3_, L_, (size_t)L_ * C3_, (size_t)L_ * C3_, (size_t)L_ * L_,
            (size_t)(2 * C_), BLL_, SCALE_, smem);
        return;
    }
    // ---- transpose + gbar path (256 threads, 8 warps) ----
    __half (*th)[34] = (__half(*)[34])smem;
    const int vb = (blockIdx.z - 16) * 8 + blockIdx.y * 4 + blockIdx.x;
    const int b = vb >> 3;
    const int l0 = (vb & 7) * 32;
    const int tx = threadIdx.x & 31, ty = threadIdx.x >> 5;

    for (int ct = 0; ct < 16; ct++) {
        const int c0 = ct * 32;
#pragma unroll
        for (int j = 0; j < 4; j++) {
            size_t idx = ((size_t)b * L_ + l0 + ty + j * 8) * C3_ + 2 * C_ + c0 + tx;
            th[ty + j * 8][tx] = qkvHi[idx];
        }
        __syncthreads();
#pragma unroll
        for (int j = 0; j < 4; j++) {
            int c = c0 + ty + j * 8;
            size_t o = ((size_t)b * C_ + c) * L_ + l0 + tx;
            gg2Hi[o] = th[tx][ty + j * 8];
        }
        __syncthreads();
    }
#pragma unroll
    for (int i = 0; i < 4; i++) {
        const int l = l0 + ty * 4 + i;
        const size_t base = ((size_t)b * L_ + l) * C3_ + 2 * C_;
        float s = 0.f;
#pragma unroll
        for (int c = tx; c < C_; c += 32)
            s += __half2float(qkvHi[base + c]);
        s = warpSum(s);
        if (tx == 0) gbar[b * L_ + l] = s * (1.f / C_);
    }
}

// ============================================================================
// prep_all: ONE launch = fp16 weight conversion (8/thread) + bias + x transpose
// ============================================================================
constexpr int PREP_WELEMS = 3 * C_ * C_ + C_ * C_ + C4_ * C_ + C_ * C4_;
constexpr int PREP_NW8 = PREP_WELEMS / 8 / 256;       // 1536
constexpr int PREP_NB = 6;
constexpr int PREP_NT = (L_ / 32) * (C_ / 32) * B_;   // 1024

__global__ void prep_all(const float* __restrict__ x,
                         const float* __restrict__ tw, const float* __restrict__ pw,
                         const float* __restrict__ gw, const float* __restrict__ wgw,
                         const float* __restrict__ c1w, const float* __restrict__ c2w,
                         const float* __restrict__ tb, const float* __restrict__ pb,
                         const float* __restrict__ gb,
                         __half* __restrict__ qkvW, __half* __restrict__ wgW,
                         __half* __restrict__ c1W, __half* __restrict__ c2W,
                         float* __restrict__ qkvb,
                         __half* __restrict__ xtHi, float* __restrict__ xt32)
{
    __shared__ float t[32][33];
    const int bid = blockIdx.x;
    if (bid < PREP_NW8) {
        constexpr int NW = C_ * C_;
        constexpr int N1 = 3 * NW;
        constexpr int N2 = N1 + NW;
        constexpr int N3 = N2 + C4_ * C_;
        const int i = (bid * 256 + threadIdx.x) * 8;
        const float* src;
        __half* dst;
        int j;
        if (i < N1) {
            j = i & (NW - 1);
            src = (i < NW) ? tw : (i < 2 * NW ? pw : gw);
            dst = qkvW + i;
        } else if (i < N2) { j = i - N1; src = wgw; dst = wgW + j; }
        else if (i < N3)   { j = i - N2; src = c1w; dst = c1W + j; }
        else               { j = i - N3; src = c2w; dst = c2W + j; }
        float4 va = *(const float4*)(src + j);
        float4 vb = *(const float4*)(src + j + 4);
        __half2 h[4];
        h[0].x = __float2half_rn(va.x); h[0].y = __float2half_rn(va.y);
        h[1].x = __float2half_rn(va.z); h[1].y = __float2half_rn(va.w);
        h[2].x = __float2half_rn(vb.x); h[2].y = __float2half_rn(vb.y);
        h[3].x = __float2half_rn(vb.z); h[3].y = __float2half_rn(vb.w);
        *(uint4*)dst = *(uint4*)h;
    } else if (bid < PREP_NW8 + PREP_NB) {
        const int j = (bid - PREP_NW8) * 256 + threadIdx.x;
        if (j < C3_)
            qkvb[j] = (j < C_) ? tb[j] : (j < 2 * C_ ? pb[j - C_] : gb[j - 2 * C_]);
    } else {
        const int tI = bid - PREP_NW8 - PREP_NB;
        const int b = tI >> 7;
        const int rem = tI & 127;
        const int c0 = (rem & 15) * 32;
        const int l0 = (rem >> 4) * 32;
        const int tx = threadIdx.x & 31, ty = threadIdx.x >> 5;
        const float* xb = x + (size_t)b * CL_;
#pragma unroll
        for (int j = 0; j < 4; j++)
            t[ty + j * 8][tx] = xb[(size_t)(c0 + ty + j * 8) * L_ + l0 + tx];
        __syncthreads();
#pragma unroll
        for (int j = 0; j < 4; j++) {
            int l = l0 + ty + j * 8;
            float v = t[tx][ty + j * 8];
            size_t o = ((size_t)b * L_ + l) * C_ + c0 + tx;
            xtHi[o] = __float2half_rn(v);
            xt32[o] = v;
        }
    }
}

// ============================================================================
// softmax_gate: warp-per-row, f16 scores in. grid (L/8, B), 256 threads.
// ============================================================================
__global__ void __launch_bounds__(256) softmax_gate(
    const __half* __restrict__ Sg,
    const __half* __restrict__ Sl,
    const float* __restrict__ gbar,
    const float* __restrict__ wlw,
    const float* __restrict__ wlb,
    __half* __restrict__ pHi,
    float* __restrict__ gate)
{
    const int w = threadIdx.x >> 5, lane = threadIdx.x & 31;
    const int l = blockIdx.x * 8 + w;
    const int b = blockIdx.y;
    const size_t row = (size_t)b * L_ + l;

    uint4 raw = *(const uint4*)(Sg + row * L_ + lane * 8);
    __half2* rh = (__half2*)&raw;
    float v[8];
#pragma unroll
    for (int i = 0; i < 4; i++) {
        float2 f = __half22float2(rh[i]);
        v[2 * i] = f.x; v[2 * i + 1] = f.y;
    }
    float mx = v[0];
#pragma unroll
    for (int i = 1; i < 8; i++) mx = fmaxf(mx, v[i]);
    mx = warpMax(mx);
    float sum = 0.f;
#pragma unroll
    for (int i = 0; i < 8; i++) { v[i] = __expf(v[i] - mx); sum += v[i]; }
    sum = warpSum(sum);
    const float inv = 1.f / sum;
    __half2 hp[4];
#pragma unroll
    for (int i = 0; i < 4; i++) {
        hp[i].x = __float2half_rn(v[2 * i] * inv);
        hp[i].y = __float2half_rn(v[2 * i + 1] * inv);
    }
    *(uint4*)(pHi + row * L_ + lane * 8) = *(uint4*)hp;

    const __half* slrow = Sl + row * L_;
    const float* gb = gbar + (size_t)b * L_;
    int m0 = l + lane - 32;
    int m1 = l + lane;
    bool v0 = (m0 >= 0) && (m0 < L_);
    bool v1 = (m1 >= 0) && (m1 < L_);
    float s0 = v0 ? __half2float(slrow[m0]) : 0.f;
    float s1 = v1 ? __half2float(slrow[m1]) : 0.f;
    float g0 = v0 ? gb[m0] : 0.f;
    float g1 = v1 ? gb[m1] : 0.f;
    float bx = warpMax(fmaxf(s0, s1));
    float e0 = __expf(s0 - bx), e1 = __expf(s1 - bx);
    float num = warpSum(e0 * g0 + e1 * g1);
    float den = warpSum(e0 + e1);
    if (lane == 0) {
        float pooled = num / den;
        float z = wlw[0] * pooled + wlb[0];
        gate[b * L_ + l] = 1.f / (1.f + __expf(-z));
    }
}

// ============================================================================
// LN1: h = gout2T*gate + xT32 ; h1 f32 + f16 at row (l*B+b), [*,C]
// ============================================================================
__global__ void ln1_kernel(const float* __restrict__ gout2T,
                           const float* __restrict__ gate,
                           const float* __restrict__ xt32,
                           const float* __restrict__ g1, const float* __restrict__ b1,
                           float* __restrict__ h1,
                           __half* __restrict__ h1hi)
{
    __shared__ float sm[16];
    int l = blockIdx.x, b = blockIdx.y, tid = threadIdx.x;
    int lane = tid & 31, w = tid >> 5;
    float gt = gate[b * L_ + l];
    size_t gbase = ((size_t)b * L_ + l) * C_;
    float v0 = fmaf(gout2T[gbase + tid], gt, xt32[gbase + tid]);
    float v1 = fmaf(gout2T[gbase + tid + 256], gt, xt32[gbase + tid + 256]);
    float s = warpSum(v0 + v1);
    float q = warpSum(v0 * v0 + v1 * v1);
    if (lane == 0) { sm[w] = s; sm[8 + w] = q; }
    __syncthreads();
    float S = 0.f, Q = 0.f;
#pragma unroll
    for (int i = 0; i < 8; i++) { S += sm[i]; Q += sm[8 + i]; }
    float mean = S * (1.f / C_);
    float var = Q * (1.f / C_) - mean * mean;
    float r = rsqrtf(var + 1e-5f);
    size_t o = ((size_t)l * B_ + b) * C_;
    float y0 = (v0 - mean) * r * g1[tid] + b1[tid];
    float y1 = (v1 - mean) * r * g1[tid + 256] + b1[tid + 256];
    h1[o + tid] = y0;
    h1[o + tid + 256] = y1;
    h1hi[o + tid] = __float2half_rn(y0);
    h1hi[o + tid + 256] = __float2half_rn(y1);
}

// ============================================================================
// LN2 v3: READ-ONCE + coalesced stores via full SMEM staging.
// grid (L/32, B), 256 threads, dynamic smem = 32*513*4 + 256 bytes.
// Stats pass reads rows coalesced, staging values in tile[32][513] (odd
// stride -> conflict-free rows AND columns). Apply pass streams columns:
// out[(b*C+c)*L + l0+lane] contiguous in lane.
// ============================================================================
constexpr int LN2_TSTRIDE = 513;
constexpr int LN2_SMEM = (32 * LN2_TSTRIDE + 64) * 4;   // 65920 B

__global__ void __launch_bounds__(256) ln2_kernel(
    const float* __restrict__ m2,
    const float* __restrict__ h1,
    const float* __restrict__ g2, const float* __restrict__ b2,
    float* __restrict__ out)
{
    extern __shared__ float smf[];
    float* tile  = smf;                         // [32][513]
    float* mean_s = smf + 32 * LN2_TSTRIDE;     // [32]
    float* inv_s  = mean_s + 32;                // [32]
    const int b = blockIdx.y;
    const int l0 = blockIdx.x * 32;
    const int lane = threadIdx.x & 31, w = threadIdx.x >> 5;

    // stats + staging: warp w handles rows l0 + w*4 + i (reads once, coalesced)
#pragma unroll
    for (int i = 0; i < 4; i++) {
        const int lr = w * 4 + i;
        const size_t base = (size_t)((l0 + lr) * B_ + b) * C_;
        float* trow = tile + lr * LN2_TSTRIDE;
        float s = 0.f, q = 0.f;
#pragma unroll 4
        for (int c = lane; c < C_; c += 32) {
            float v = m2[base + c] + h1[base + c];
            trow[c] = v;
            s += v; q += v * v;
        }
        s = warpSum(s); q = warpSum(q);
        if (lane == 0) {
            float mean = s * (1.f / C_);
            float var = q * (1.f / C_) - mean * mean;
            mean_s[lr] = mean;
            inv_s[lr] = rsqrtf(var + 1e-5f);
        }
    }
    __syncthreads();

    // apply + coalesced stores: warp w handles cols c = w*64 .. w*64+63
    const float mean = mean_s[lane];
    const float inv = inv_s[lane];
#pragma unroll 8
    for (int rep = 0; rep < 64; rep++) {
        const int c = w * 64 + rep;
        const float gg = g2[c], bb = b2[c];
        float v = tile[lane * LN2_TSTRIDE + c];
        out[((size_t)b * C_ + c) * L_ + l0 + lane] = (v - mean) * inv * gg + bb;
    }
}

} // namespace

// ============================================================================
// Host launcher
// ============================================================================
extern "C" void kernel_launch(void* const* d_in, const int* in_sizes, int n_in,
                              void* d_out, int out_size)
{
    (void)in_sizes; (void)n_in; (void)out_size;
    float* scratch = nullptr;
    cudaGetSymbolAddress((void**)&scratch, d_scratch);

    const float* x       = (const float*)d_in[0];
    const float* theta_w = (const float*)d_in[1];
    const float* theta_b = (const float*)d_in[2];
    const float* phi_w   = (const float*)d_in[3];
    const float* phi_b   = (const float*)d_in[4];
    const float* g_w     = (const float*)d_in[5];
    const float* g_b     = (const float*)d_in[6];
    const float* wl_w    = (const float*)d_in[7];
    const float* wl_b    = (const float*)d_in[8];
    const float* wg_w    = (const float*)d_in[9];
    const float* wg_b    = (const float*)d_in[10];
    const float* conv1_w = (const float*)d_in[11];
    const float* conv1_b = (const float*)d_in[12];
    const float* conv2_w = (const float*)d_in[13];
    const float* conv2_b = (const float*)d_in[14];
    const float* ln1_g   = (const float*)d_in[15];
    const float* ln1_b   = (const float*)d_in[16];
    const float* ln2_g   = (const float*)d_in[17];
    const float* ln2_b   = (const float*)d_in[18];
    float* out = (float*)d_out;

    __half* xtHi   = (__half*)(scratch + OFF_XT_HI);
    float* xt32    = scratch + OFF_XT32;
    __half* wqkvW  = (__half*)(scratch + OFF_WQKV_HI);
    float* qkv_b   = scratch + OFF_QKV_B;
    __half* wwgW   = (__half*)(scratch + OFF_WWG_HI);
    __half* c1W    = (__half*)(scratch + OFF_C1WHI);
    __half* c2W    = (__half*)(scratch + OFF_C2WHI);
    __half* qkvHi  = (__half*)(scratch + OFF_QKVT_HI);
    __half* SgH    = (__half*)(scratch + OFF_SG);
    __half* gpHi   = (__half*)(scratch + OFF_GP_HI);
    __half* gg2Hi  = (__half*)(scratch + OFF_GG2_HI);
    float* gbar    = scratch + OFF_GBAR;
    float* gate    = scratch + OFF_GATE;
    __half* goHi   = (__half*)(scratch + OFF_GOUTT_HI);
    float* gout2T  = scratch + OFF_GOUT2T;
    float* h1      = scratch + OFF_H1;
    __half* h1Hi   = (__half*)(scratch + OFF_H1HI);
    __half* m1Hi   = (__half*)(scratch + OFF_M1HI);
    float* m2      = scratch + OFF_M2;

    // SMEM: BN=64 KB=64 3st: 82944 (2 CTA/SM) ; BN=128 KB=32 2st: 40960
    constexpr int SM_64  = 82944;
    constexpr int SM_128 = 40960;
    cudaFuncSetAttribute(sgsl_gtrans,                      cudaFuncAttributeMaxDynamicSharedMemorySize, SM_64);
    cudaFuncSetAttribute(gemm_mma<64, 2, 0, 0, 3, 64, 2>,  cudaFuncAttributeMaxDynamicSharedMemorySize, SM_64);
    cudaFuncSetAttribute(gemm_mma<64, 0, 0, 0, 3, 64, 2>,  cudaFuncAttributeMaxDynamicSharedMemorySize, SM_64);
    cudaFuncSetAttribute(gemm_mma<128, 2, 0, 0, 2, 32, 2>, cudaFuncAttributeMaxDynamicSharedMemorySize, SM_128);
    cudaFuncSetAttribute(gemm_mma<128, 2, 1, 0, 2, 32, 2>, cudaFuncAttributeMaxDynamicSharedMemorySize, SM_128);
    cudaFuncSetAttribute(ln2_kernel, cudaFuncAttributeMaxDynamicSharedMemorySize, LN2_SMEM);

    // 0) prep
    prep_all<<<PREP_NW8 + PREP_NB + PREP_NT, 256>>>(
        x, theta_w, phi_w, g_w, wg_w, conv1_w, conv2_w, theta_b, phi_b, g_b,
        wqkvW, wwgW, c1W, c2W, qkv_b, xtHi, xt32);

    // 1) fused qkv -> f16
    {
        dim3 grid(C3_ / 128, L_ / 128, B_);
        gemm_mma<128, 2, 0, 0, 2, 32, 2><<<grid, 256, SM_128>>>(
            xtHi, wqkvW, qkv_b, nullptr, qkvHi,
            C_, C_, C_, C3_, (size_t)L_ * C_, 0, (size_t)L_ * C3_, 0, 0, 1.f);
    }

    // 2) Sg & Sl (f16 scores) + g-transpose + gbar, ONE launch
    {
        dim3 grid(L_ / 64, L_ / 128, 16 + 8);
        sgsl_gtrans<<<grid, 256, SM_64>>>(qkvHi, SgH, gg2Hi, gbar);
    }

    // 3) fused softmax + local gate (warp-per-row, f16 in)
    softmax_gate<<<dim3(L_ / 8, B_), 256>>>(SgH, SgH + BLL_, gbar,
                                            wl_w, wl_b, gpHi, gate);

    // 4) goutT = gp @ gg2^T -> f16 ; gout2T = goutT @ wg^T + wg_b -> f32
    {
        dim3 grid(C_ / 64, L_ / 128, B_);
        gemm_mma<64, 2, 0, 0, 3, 64, 2><<<grid, 256, SM_64>>>(
            gpHi, gg2Hi, nullptr, nullptr, goHi,
            L_, L_, L_, C_, (size_t)L_ * L_, (size_t)CL_, (size_t)L_ * C_, 0, 0, 1.f);
        gemm_mma<64, 0, 0, 0, 3, 64, 2><<<grid, 256, SM_64>>>(
            goHi, wwgW, wg_b, gout2T, nullptr,
            C_, C_, C_, C_, (size_t)L_ * C_, 0, (size_t)L_ * C_, 0, 0, 1.f);
    }

    // 5) LN1 -> h1 (f32 + f16)
    ln1_kernel<<<dim3(L_, B_), 256>>>(gout2T, gate, xt32, ln1_g, ln1_b, h1, h1Hi);

    // 6) MLP1: m1 = Mish(h1 @ conv1^T + b) -> f16
    {
        dim3 grid(C4_ / 128, NR_ / 128, 1);
        gemm_mma<128, 2, 1, 0, 2, 32, 2><<<grid, 256, SM_128>>>(
            h1Hi, c1W, conv1_b, nullptr, m1Hi,
            C_, C_, C_, C4_, 0, 0, 0, 0, 0, 1.f);
    }

    // 7) MLP2: m2 = m1 @ conv2^T + b -> f32
    {
        dim3 grid(C_ / 64, NR_ / 128, 1);
        gemm_mma<64, 0, 0, 0, 3, 64, 2><<<grid, 256, SM_64>>>(
            m1Hi, c2W, conv2_b, m2, nullptr,
            C4_, C4_, C4_, C_, 0, 0, 0, 0, 0, 1.f);
    }

    // 8) LN2: read-once + coalesced transpose out
    ln2_kernel<<<dim3(L_ / 32, B_), 256, LN2_SMEM>>>(m2, h1, ln2_g, ln2_b, out);
}

// round 17
// speedup vs baseline: 1.3221x; 1.0310x over previous
#include <cuda_runtime.h>
#include <cuda_fp16.h>
#include <math.h>
#include <stdint.h>

// ============================================================================
// Problem constants
// ============================================================================
namespace {
constexpr int B_ = 8, C_ = 512, L_ = 256;
constexpr int CL_ = C_ * L_;           // 131072
constexpr int C3_ = 3 * C_;            // 1536
constexpr int C4_ = 4 * C_;            // 2048
constexpr int NR_ = L_ * B_;           // 2048
constexpr size_t BLL_ = (size_t)B_ * L_ * L_;
constexpr float SCALE_ = 0.044194173824159216f; // 512^-0.5

// ---------------- scratch offsets (float units) ----------------
constexpr size_t OFF_XT_HI   = 0;                                    // f16 [B,L,C]
constexpr size_t OFF_XT32    = OFF_XT_HI   + (size_t)B_ * CL_ / 2;   // f32 [B,L,C]
constexpr size_t OFF_WQKV_HI = OFF_XT32    + (size_t)B_ * CL_;       // f16 [3C,C]
constexpr size_t OFF_QKV_B   = OFF_WQKV_HI + (size_t)C3_ * C_ / 2;   // f32 [1536]
constexpr size_t OFF_WWG_HI  = OFF_QKV_B   + 1536;
constexpr size_t OFF_C1WHI   = OFF_WWG_HI  + (size_t)C_ * C_ / 2;
constexpr size_t OFF_C2WHI   = OFF_C1WHI   + (size_t)C4_ * C_ / 2;
constexpr size_t OFF_QKVT_HI = OFF_C2WHI   + (size_t)C_ * C4_ / 2;   // f16 [B,L,3C]
constexpr size_t OFF_SG      = OFF_QKVT_HI + (size_t)B_ * L_ * C3_ / 2; // f16 [2][B,L,L]
constexpr size_t OFF_GP_HI   = OFF_SG      + BLL_;                   // f16 [B,L,L]
constexpr size_t OFF_GWG     = OFF_GP_HI   + BLL_ / 2;               // f16 [B,C,L]
constexpr size_t OFF_GBAR    = OFF_GWG     + (size_t)B_ * CL_ / 2;
constexpr size_t OFF_GATE    = OFF_GBAR    + (size_t)B_ * L_;
constexpr size_t OFF_GOUT2T  = OFF_GATE    + (size_t)B_ * L_;        // f32 [B,L,C]
constexpr size_t OFF_H1      = OFF_GOUT2T  + (size_t)B_ * CL_;       // f32 [NR,C]
constexpr size_t OFF_H1HI    = OFF_H1      + (size_t)NR_ * C_;       // f16 [NR,C]
constexpr size_t OFF_M1HI    = OFF_H1HI    + (size_t)NR_ * C_ / 2;   // f16 [NR,C4]
constexpr size_t OFF_M2      = OFF_M1HI    + (size_t)NR_ * C4_ / 2;  // f32 [NR,C]
constexpr size_t SCRATCH_TOTAL = OFF_M2    + (size_t)NR_ * C_;
} // namespace

__device__ __align__(256) float d_scratch[SCRATCH_TOTAL];

// ============================================================================
// PTX helpers — sm_80-era only (mma.sync / ldmatrix / cp.async).
// ============================================================================
__device__ __forceinline__ uint32_t smem_to_u32(const void* p) {
    uint32_t a;
    asm("{ .reg .u64 t; cvta.to.shared.u64 t, %1; cvt.u32.u64 %0, t; }" : "=r"(a) : "l"(p));
    return a;
}
__device__ __forceinline__ void ldmat4(uint32_t (&r)[4], uint32_t addr) {
    asm volatile("ldmatrix.sync.aligned.m8n8.x4.shared.b16 {%0,%1,%2,%3}, [%4];"
                 : "=r"(r[0]), "=r"(r[1]), "=r"(r[2]), "=r"(r[3]) : "r"(addr));
}
__device__ __forceinline__ void mma16816(float (&d)[4], const uint32_t (&a)[4], const uint32_t b0, const uint32_t b1) {
    asm volatile("mma.sync.aligned.m16n8k16.row.col.f32.f16.f16.f32 "
                 "{%0,%1,%2,%3}, {%4,%5,%6,%7}, {%8,%9}, {%0,%1,%2,%3};"
                 : "+f"(d[0]), "+f"(d[1]), "+f"(d[2]), "+f"(d[3])
                 : "r"(a[0]), "r"(a[1]), "r"(a[2]), "r"(a[3]), "r"(b0), "r"(b1));
}
__device__ __forceinline__ void cp16(uint32_t saddr, const void* g) {
    asm volatile("cp.async.cg.shared.global [%0], [%1], 16;" :: "r"(saddr), "l"(g));
}
#define CP_COMMIT() asm volatile("cp.async.commit_group;" ::: "memory")
template <int N>
__device__ __forceinline__ void cp_wait() {
    asm volatile("cp.async.wait_group %0;" :: "n"(N) : "memory");
}

namespace {

__device__ __forceinline__ float warpSum(float v) {
#pragma unroll
    for (int o = 16; o; o >>= 1) v += __shfl_xor_sync(0xffffffffu, v, o);
    return v;
}
__device__ __forceinline__ float warpMax(float v) {
#pragma unroll
    for (int o = 16; o; o >>= 1) v = fmaxf(v, __shfl_xor_sync(0xffffffffu, v, o));
    return v;
}
__device__ __forceinline__ float mishf(float v) {
    float sp = fmaxf(v, 0.f) + log1pf(__expf(-fabsf(v)));
    return v * tanhf(sp);
}

// ============================================================================
// fp16 tensor-core GEMM body (explicit virtual block indices bx, by, zz).
// 1-pass fp16 NT: A [M,K] K-contig (lda) ; B [N,K] K-contig (ldb).
// D = A·B^T (fp32 accum); v = scale*D (+ biasN); ACT=1 -> mish.
// OUTFMT 0: f32 ; 2: f16. FUSE=1: zz -> (sel = zz>>3, b = zz&7).
// ============================================================================
template <int BN, int OUTFMT, int ACT, int FUSE, int STAGES, int KB, int WM>
__device__ __forceinline__ void gemm_body(
    int bx, int by, int zz,
    const __half* __restrict__ A, const __half* __restrict__ Bm,
    const float* __restrict__ biasN,
    float* __restrict__ outF, __half* __restrict__ outH,
    int K, int lda, int ldb, int ldOut,
    size_t sA, size_t sB, size_t sO, size_t selB, size_t selO, float scale,
    char* smem)
{
    constexpr int BM = 128;
    constexpr int TPB = WM * 128;
    constexpr int MI = BM / (WM * 16);
    constexpr int SROW = KB * 2 + 16;
    constexpr int CHR = KB / 8;
    constexpr int ATILE = BM * SROW;
    constexpr int BTILE = BN * SROW;
    constexpr int STAGE = ATILE + BTILE;
    constexpr int WN = BN / 4;
    constexpr int NFRAG = WN / 8;
    constexpr int NKS = KB / 16;

    const uint32_t sb = smem_to_u32(smem);
    const int tid = threadIdx.x, lane = tid & 31, wid = tid >> 5;
    const int wm = wid & (WM - 1), wn = wid / WM;
    const int m0 = by * BM, n0 = bx * BN;
    const int b = FUSE ? (zz & 7) : zz;
    const int sel = FUSE ? (zz >> 3) : 0;

    A += (size_t)b * sA;
    Bm += (size_t)b * sB + (size_t)sel * selB;
    if (OUTFMT == 0) outF += (size_t)b * sO + (size_t)sel * selO;
    else             outH += (size_t)b * sO + (size_t)sel * selO;

    float acc[MI][NFRAG][4];
#pragma unroll
    for (int i = 0; i < MI; i++)
#pragma unroll
        for (int j = 0; j < NFRAG; j++)
#pragma unroll
            for (int q = 0; q < 4; q++) acc[i][j][q] = 0.f;

    auto load_stage = [&](int ch, int st) {
        const int k0 = ch * KB;
        const uint32_t base = sb + st * STAGE;
#pragma unroll
        for (int c = tid; c < BM * CHR; c += TPB) {
            int r = c / CHR, cc = c % CHR;
            cp16(base + r * SROW + cc * 16, A + (size_t)(m0 + r) * lda + k0 + cc * 8);
        }
#pragma unroll
        for (int c = tid; c < BN * CHR; c += TPB) {
            int r = c / CHR, cc = c % CHR;
            cp16(base + ATILE + r * SROW + cc * 16, Bm + (size_t)(n0 + r) * ldb + k0 + cc * 8);
        }
        CP_COMMIT();
    };

    const int nch = K / KB;
#pragma unroll
    for (int s = 0; s < STAGES - 1; s++) load_stage(s, s);

    int cs = 0;
    int ps = (STAGES - 1) % STAGES;
    for (int ch = 0; ch < nch; ch++) {
        cp_wait<STAGES - 2>();
        __syncthreads();
        const int pf = ch + STAGES - 1;
        if (pf < nch) load_stage(pf, ps);
        else CP_COMMIT();

        const uint32_t aBase = sb + cs * STAGE;
        const uint32_t bBase = aBase + ATILE;
#pragma unroll
        for (int ks = 0; ks < NKS; ks++) {
            const uint32_t colOff = (uint32_t)(ks * 2 + (lane >> 4)) * 16;
            uint32_t a_f[MI][4];
#pragma unroll
            for (int mi = 0; mi < MI; mi++) {
                uint32_t addr = aBase + (uint32_t)(wm * (MI * 16) + mi * 16 + (lane & 15)) * SROW + colOff;
                ldmat4(a_f[mi], addr);
            }
#pragma unroll
            for (int nt = 0; nt < NFRAG / 2; nt++) {
                uint32_t addr = bBase + (uint32_t)(wn * WN + nt * 16 + (lane & 15)) * SROW + colOff;
                uint32_t bf[4];
                ldmat4(bf, addr);
#pragma unroll
                for (int half = 0; half < 2; half++) {
                    const int ni = nt * 2 + half;
#pragma unroll
                    for (int mi = 0; mi < MI; mi++)
                        mma16816(acc[mi][ni], a_f[mi], bf[half], bf[2 + half]);
                }
            }
        }
        cs = (cs + 1 == STAGES) ? 0 : cs + 1;
        ps = (ps + 1 == STAGES) ? 0 : ps + 1;
    }

    // ---------------- epilogue ----------------
    const int g = lane >> 2, tg = lane & 3;
#pragma unroll
    for (int mi = 0; mi < MI; mi++) {
#pragma unroll
        for (int ni = 0; ni < NFRAG; ni++) {
            const int col = n0 + wn * WN + ni * 8 + tg * 2;
            const float b0 = biasN ? biasN[col] : 0.f;
            const float b1 = biasN ? biasN[col + 1] : 0.f;
#pragma unroll
            for (int h = 0; h < 2; h++) {
                const int row = m0 + wm * (MI * 16) + mi * 16 + g + h * 8;
                float v0 = acc[mi][ni][h * 2 + 0] * scale + b0;
                float v1 = acc[mi][ni][h * 2 + 1] * scale + b1;
                if (ACT == 1) { v0 = mishf(v0); v1 = mishf(v1); }
                const size_t o = (size_t)row * ldOut + col;
                if (OUTFMT == 0) {
                    float2 fp; fp.x = v0; fp.y = v1;
                    *(float2*)(outF + o) = fp;
                } else {
                    __half2 hp;
                    hp.x = __float2half_rn(v0);
                    hp.y = __float2half_rn(v1);
                    *(__half2*)(outH + o) = hp;
                }
            }
        }
    }
}

template <int BN, int OUTFMT, int ACT, int FUSE, int STAGES, int KB, int WM>
__global__ void __launch_bounds__(WM * 128) gemm_mma(
    const __half* __restrict__ A, const __half* __restrict__ Bm,
    const float* __restrict__ biasN,
    float* __restrict__ outF, __half* __restrict__ outH,
    int K, int lda, int ldb, int ldOut,
    size_t sA, size_t sB, size_t sO, size_t selB, size_t selO, float scale)
{
    extern __shared__ char smem[];
    gemm_body<BN, OUTFMT, ACT, FUSE, STAGES, KB, WM>(
        blockIdx.x, blockIdx.y, blockIdx.z,
        A, Bm, biasN, outF, outH,
        K, lda, ldb, ldOut, sA, sB, sO, selB, selO, scale, smem);
}

// ============================================================================
// Fused post-qkv launch. Grid (4, 2, 33), 256 threads, smem 82944.
//   z <  16: Sg/Sl scores (f16), FUSE (sel|b)               — 128 tiles
//   16<=z<32: gwg[b,c,m] = sum_cc wg[c,cc]*g[b,cc,m] (f16)  — 128 tiles
//             tile t=(z-16)*8+by*4+bx: b=t>>4, by'=(t&15)>>2, bx'=t&3
//   z == 32: gbar[b,l] = mean_c g[b,c,l]                    — 8 blocks (b=by*4+bx)
// ============================================================================
__global__ void __launch_bounds__(256) sgsl_gwg(
    const __half* __restrict__ qkvHi,
    const __half* __restrict__ wgW,
    __half* __restrict__ SgH,
    __half* __restrict__ gwgH,
    float* __restrict__ gbar)
{
    extern __shared__ char smem[];
    const int z = blockIdx.z;
    if (z < 16) {
        gemm_body<64, 2, 0, 1, 3, 64, 2>(
            blockIdx.x, blockIdx.y, z,
            qkvHi + C_, qkvHi, nullptr, nullptr, SgH,
            C_, C3_, C3_, L_, (size_t)L_ * C3_, (size_t)L_ * C3_, (size_t)L_ * L_,
            (size_t)(2 * C_), BLL_, SCALE_, smem);
        return;
    }
    if (z < 32) {
        const int t = (z - 16) * 8 + blockIdx.y * 4 + blockIdx.x;
        const int b = t >> 4;
        const int byv = (t & 15) >> 2;
        const int bxv = t & 3;
        // M=C (rows c of wg), N=L (cols m), K=C (cc). A=wgW [C,C], B=g-slice.
        gemm_body<64, 2, 0, 0, 3, 64, 2>(
            bxv, byv, b,
            wgW, qkvHi + 2 * C_, nullptr, nullptr, gwgH,
            C_, C_, C3_, L_, 0, (size_t)L_ * C3_, (size_t)CL_, 0, 0, 1.f, smem);
        return;
    }
    // ---- gbar: block handles one batch b; warp w covers l = w*32..w*32+31 ----
    const int b = blockIdx.y * 4 + blockIdx.x;
    const int lane = threadIdx.x & 31, w = threadIdx.x >> 5;
    for (int i = 0; i < 32; i++) {
        const int l = w * 32 + i;
        const size_t base = ((size_t)b * L_ + l) * C3_ + 2 * C_;
        float s = 0.f;
#pragma unroll
        for (int c = lane; c < C_; c += 32)
            s += __half2float(qkvHi[base + c]);
        s = warpSum(s);
        if (lane == 0) gbar[b * L_ + l] = s * (1.f / C_);
    }
}

// ============================================================================
// prep_all: ONE launch = fp16 weight conversion (8/thread) + bias + x transpose
// ============================================================================
constexpr int PREP_WELEMS = 3 * C_ * C_ + C_ * C_ + C4_ * C_ + C_ * C4_;
constexpr int PREP_NW8 = PREP_WELEMS / 8 / 256;       // 1536
constexpr int PREP_NB = 6;
constexpr int PREP_NT = (L_ / 32) * (C_ / 32) * B_;   // 1024

__global__ void prep_all(const float* __restrict__ x,
                         const float* __restrict__ tw, const float* __restrict__ pw,
                         const float* __restrict__ gw, const float* __restrict__ wgw,
                         const float* __restrict__ c1w, const float* __restrict__ c2w,
                         const float* __restrict__ tb, const float* __restrict__ pb,
                         const float* __restrict__ gb,
                         __half* __restrict__ qkvW, __half* __restrict__ wgW,
                         __half* __restrict__ c1W, __half* __restrict__ c2W,
                         float* __restrict__ qkvb,
                         __half* __restrict__ xtHi, float* __restrict__ xt32)
{
    __shared__ float t[32][33];
    const int bid = blockIdx.x;
    if (bid < PREP_NW8) {
        constexpr int NW = C_ * C_;
        constexpr int N1 = 3 * NW;
        constexpr int N2 = N1 + NW;
        constexpr int N3 = N2 + C4_ * C_;
        const int i = (bid * 256 + threadIdx.x) * 8;
        const float* src;
        __half* dst;
        int j;
        if (i < N1) {
            j = i & (NW - 1);
            src = (i < NW) ? tw : (i < 2 * NW ? pw : gw);
            dst = qkvW + i;
        } else if (i < N2) { j = i - N1; src = wgw; dst = wgW + j; }
        else if (i < N3)   { j = i - N2; src = c1w; dst = c1W + j; }
        else               { j = i - N3; src = c2w; dst = c2W + j; }
        float4 va = *(const float4*)(src + j);
        float4 vb = *(const float4*)(src + j + 4);
        __half2 h[4];
        h[0].x = __float2half_rn(va.x); h[0].y = __float2half_rn(va.y);
        h[1].x = __float2half_rn(va.z); h[1].y = __float2half_rn(va.w);
        h[2].x = __float2half_rn(vb.x); h[2].y = __float2half_rn(vb.y);
        h[3].x = __float2half_rn(vb.z); h[3].y = __float2half_rn(vb.w);
        *(uint4*)dst = *(uint4*)h;
    } else if (bid < PREP_NW8 + PREP_NB) {
        const int j = (bid - PREP_NW8) * 256 + threadIdx.x;
        if (j < C3_)
            qkvb[j] = (j < C_) ? tb[j] : (j < 2 * C_ ? pb[j - C_] : gb[j - 2 * C_]);
    } else {
        const int tI = bid - PREP_NW8 - PREP_NB;
        const int b = tI >> 7;
        const int rem = tI & 127;
        const int c0 = (rem & 15) * 32;
        const int l0 = (rem >> 4) * 32;
        const int tx = threadIdx.x & 31, ty = threadIdx.x >> 5;
        const float* xb = x + (size_t)b * CL_;
#pragma unroll
        for (int j = 0; j < 4; j++)
            t[ty + j * 8][tx] = xb[(size_t)(c0 + ty + j * 8) * L_ + l0 + tx];
        __syncthreads();
#pragma unroll
        for (int j = 0; j < 4; j++) {
            int l = l0 + ty + j * 8;
            float v = t[tx][ty + j * 8];
            size_t o = ((size_t)b * L_ + l) * C_ + c0 + tx;
            xtHi[o] = __float2half_rn(v);
            xt32[o] = v;
        }
    }
}

// ============================================================================
// softmax_gate: warp-per-row, f16 scores in. grid (L/8, B), 256 threads.
// ============================================================================
__global__ void __launch_bounds__(256) softmax_gate(
    const __half* __restrict__ Sg,
    const __half* __restrict__ Sl,
    const float* __restrict__ gbar,
    const float* __restrict__ wlw,
    const float* __restrict__ wlb,
    __half* __restrict__ pHi,
    float* __restrict__ gate)
{
    const int w = threadIdx.x >> 5, lane = threadIdx.x & 31;
    const int l = blockIdx.x * 8 + w;
    const int b = blockIdx.y;
    const size_t row = (size_t)b * L_ + l;

    uint4 raw = *(const uint4*)(Sg + row * L_ + lane * 8);
    __half2* rh = (__half2*)&raw;
    float v[8];
#pragma unroll
    for (int i = 0; i < 4; i++) {
        float2 f = __half22float2(rh[i]);
        v[2 * i] = f.x; v[2 * i + 1] = f.y;
    }
    float mx = v[0];
#pragma unroll
    for (int i = 1; i < 8; i++) mx = fmaxf(mx, v[i]);
    mx = warpMax(mx);
    float sum = 0.f;
#pragma unroll
    for (int i = 0; i < 8; i++) { v[i] = __expf(v[i] - mx); sum += v[i]; }
    sum = warpSum(sum);
    const float inv = 1.f / sum;
    __half2 hp[4];
#pragma unroll
    for (int i = 0; i < 4; i++) {
        hp[i].x = __float2half_rn(v[2 * i] * inv);
        hp[i].y = __float2half_rn(v[2 * i + 1] * inv);
    }
    *(uint4*)(pHi + row * L_ + lane * 8) = *(uint4*)hp;

    const __half* slrow = Sl + row * L_;
    const float* gb = gbar + (size_t)b * L_;
    int m0 = l + lane - 32;
    int m1 = l + lane;
    bool v0 = (m0 >= 0) && (m0 < L_);
    bool v1 = (m1 >= 0) && (m1 < L_);
    float s0 = v0 ? __half2float(slrow[m0]) : 0.f;
    float s1 = v1 ? __half2float(slrow[m1]) : 0.f;
    float g0 = v0 ? gb[m0] : 0.f;
    float g1 = v1 ? gb[m1] : 0.f;
    float bx = warpMax(fmaxf(s0, s1));
    float e0 = __expf(s0 - bx), e1 = __expf(s1 - bx);
    float num = warpSum(e0 * g0 + e1 * g1);
    float den = warpSum(e0 + e1);
    if (lane == 0) {
        float pooled = num / den;
        float z = wlw[0] * pooled + wlb[0];
        gate[b * L_ + l] = 1.f / (1.f + __expf(-z));
    }
}

// ============================================================================
// LN1: h = gout2T*gate + xT32 ; h1 f32 + f16 at row (l*B+b), [*,C]
// ============================================================================
__global__ void ln1_kernel(const float* __restrict__ gout2T,
                           const float* __restrict__ gate,
                           const float* __restrict__ xt32,
                           const float* __restrict__ g1, const float* __restrict__ b1,
                           float* __restrict__ h1,
                           __half* __restrict__ h1hi)
{
    __shared__ float sm[16];
    int l = blockIdx.x, b = blockIdx.y, tid = threadIdx.x;
    int lane = tid & 31, w = tid >> 5;
    float gt = gate[b * L_ + l];
    size_t gbase = ((size_t)b * L_ + l) * C_;
    float v0 = fmaf(gout2T[gbase + tid], gt, xt32[gbase + tid]);
    float v1 = fmaf(gout2T[gbase + tid + 256], gt, xt32[gbase + tid + 256]);
    float s = warpSum(v0 + v1);
    float q = warpSum(v0 * v0 + v1 * v1);
    if (lane == 0) { sm[w] = s; sm[8 + w] = q; }
    __syncthreads();
    float S = 0.f, Q = 0.f;
#pragma unroll
    for (int i = 0; i < 8; i++) { S += sm[i]; Q += sm[8 + i]; }
    float mean = S * (1.f / C_);
    float var = Q * (1.f / C_) - mean * mean;
    float r = rsqrtf(var + 1e-5f);
    size_t o = ((size_t)l * B_ + b) * C_;
    float y0 = (v0 - mean) * r * g1[tid] + b1[tid];
    float y1 = (v1 - mean) * r * g1[tid + 256] + b1[tid + 256];
    h1[o + tid] = y0;
    h1[o + tid + 256] = y1;
    h1hi[o + tid] = __float2half_rn(y0);
    h1hi[o + tid + 256] = __float2half_rn(y1);
}

// ============================================================================
// LN2 v3: READ-ONCE + coalesced stores via full SMEM staging.
// ============================================================================
constexpr int LN2_TSTRIDE = 513;
constexpr int LN2_SMEM = (32 * LN2_TSTRIDE + 64) * 4;   // 65920 B

__global__ void __launch_bounds__(256) ln2_kernel(
    const float* __restrict__ m2,
    const float* __restrict__ h1,
    const float* __restrict__ g2, const float* __restrict__ b2,
    float* __restrict__ out)
{
    extern __shared__ float smf[];
    float* tile  = smf;
    float* mean_s = smf + 32 * LN2_TSTRIDE;
    float* inv_s  = mean_s + 32;
    const int b = blockIdx.y;
    const int l0 = blockIdx.x * 32;
    const int lane = threadIdx.x & 31, w = threadIdx.x >> 5;

#pragma unroll
    for (int i = 0; i < 4; i++) {
        const int lr = w * 4 + i;
        const size_t base = (size_t)((l0 + lr) * B_ + b) * C_;
        float* trow = tile + lr * LN2_TSTRIDE;
        float s = 0.f, q = 0.f;
#pragma unroll 4
        for (int c = lane; c < C_; c += 32) {
            float v = m2[base + c] + h1[base + c];
            trow[c] = v;
            s += v; q += v * v;
        }
        s = warpSum(s); q = warpSum(q);
        if (lane == 0) {
            float mean = s * (1.f / C_);
            float var = q * (1.f / C_) - mean * mean;
            mean_s[lr] = mean;
            inv_s[lr] = rsqrtf(var + 1e-5f);
        }
    }
    __syncthreads();

    const float mean = mean_s[lane];
    const float inv = inv_s[lane];
#pragma unroll 8
    for (int rep = 0; rep < 64; rep++) {
        const int c = w * 64 + rep;
        const float gg = g2[c], bb = b2[c];
        float v = tile[lane * LN2_TSTRIDE + c];
        out[((size_t)b * C_ + c) * L_ + l0 + lane] = (v - mean) * inv * gg + bb;
    }
}

} // namespace

// ============================================================================
// Host launcher — 8 serial phases
// ============================================================================
extern "C" void kernel_launch(void* const* d_in, const int* in_sizes, int n_in,
                              void* d_out, int out_size)
{
    (void)in_sizes; (void)n_in; (void)out_size;
    float* scratch = nullptr;
    cudaGetSymbolAddress((void**)&scratch, d_scratch);

    const float* x       = (const float*)d_in[0];
    const float* theta_w = (const float*)d_in[1];
    const float* theta_b = (const float*)d_in[2];
    const float* phi_w   = (const float*)d_in[3];
    const float* phi_b   = (const float*)d_in[4];
    const float* g_w     = (const float*)d_in[5];
    const float* g_b     = (const float*)d_in[6];
    const float* wl_w    = (const float*)d_in[7];
    const float* wl_b    = (const float*)d_in[8];
    const float* wg_w    = (const float*)d_in[9];
    const float* wg_b    = (const float*)d_in[10];
    const float* conv1_w = (const float*)d_in[11];
    const float* conv1_b = (const float*)d_in[12];
    const float* conv2_w = (const float*)d_in[13];
    const float* conv2_b = (const float*)d_in[14];
    const float* ln1_g   = (const float*)d_in[15];
    const float* ln1_b   = (const float*)d_in[16];
    const float* ln2_g   = (const float*)d_in[17];
    const float* ln2_b   = (const float*)d_in[18];
    float* out = (float*)d_out;

    __half* xtHi   = (__half*)(scratch + OFF_XT_HI);
    float* xt32    = scratch + OFF_XT32;
    __half* wqkvW  = (__half*)(scratch + OFF_WQKV_HI);
    float* qkv_b   = scratch + OFF_QKV_B;
    __half* wwgW   = (__half*)(scratch + OFF_WWG_HI);
    __half* c1W    = (__half*)(scratch + OFF_C1WHI);
    __half* c2W    = (__half*)(scratch + OFF_C2WHI);
    __half* qkvHi  = (__half*)(scratch + OFF_QKVT_HI);
    __half* SgH    = (__half*)(scratch + OFF_SG);
    __half* gpHi   = (__half*)(scratch + OFF_GP_HI);
    __half* gwgH   = (__half*)(scratch + OFF_GWG);
    float* gbar    = scratch + OFF_GBAR;
    float* gate    = scratch + OFF_GATE;
    float* gout2T  = scratch + OFF_GOUT2T;
    float* h1      = scratch + OFF_H1;
    __half* h1Hi   = (__half*)(scratch + OFF_H1HI);
    __half* m1Hi   = (__half*)(scratch + OFF_M1HI);
    float* m2      = scratch + OFF_M2;

    // SMEM: BN=64 KB=64 3st: 82944 (2 CTA/SM) ; BN=128 KB=32 2st: 40960
    constexpr int SM_64  = 82944;
    constexpr int SM_128 = 40960;
    cudaFuncSetAttribute(sgsl_gwg,                         cudaFuncAttributeMaxDynamicSharedMemorySize, SM_64);
    cudaFuncSetAttribute(gemm_mma<64, 0, 0, 0, 3, 64, 2>,  cudaFuncAttributeMaxDynamicSharedMemorySize, SM_64);
    cudaFuncSetAttribute(gemm_mma<128, 2, 0, 0, 2, 32, 2>, cudaFuncAttributeMaxDynamicSharedMemorySize, SM_128);
    cudaFuncSetAttribute(gemm_mma<128, 2, 1, 0, 2, 32, 2>, cudaFuncAttributeMaxDynamicSharedMemorySize, SM_128);
    cudaFuncSetAttribute(ln2_kernel, cudaFuncAttributeMaxDynamicSharedMemorySize, LN2_SMEM);

    // 0) prep
    prep_all<<<PREP_NW8 + PREP_NB + PREP_NT, 256>>>(
        x, theta_w, phi_w, g_w, wg_w, conv1_w, conv2_w, theta_b, phi_b, g_b,
        wqkvW, wwgW, c1W, c2W, qkv_b, xtHi, xt32);

    // 1) fused qkv -> f16
    {
        dim3 grid(C3_ / 128, L_ / 128, B_);
        gemm_mma<128, 2, 0, 0, 2, 32, 2><<<grid, 256, SM_128>>>(
            xtHi, wqkvW, qkv_b, nullptr, qkvHi,
            C_, C_, C_, C3_, (size_t)L_ * C_, 0, (size_t)L_ * C3_, 0, 0, 1.f);
    }

    // 2) Sg/Sl + gwg (= wg @ g, reassociated) + gbar — ONE launch
    {
        dim3 grid(4, 2, 33);
        sgsl_gwg<<<grid, 256, SM_64>>>(qkvHi, wwgW, SgH, gwgH, gbar);
    }

    // 3) fused softmax + local gate
    softmax_gate<<<dim3(L_ / 8, B_), 256>>>(SgH, SgH + BLL_, gbar,
                                            wl_w, wl_b, gpHi, gate);

    // 4) gout2T = gp @ gwg^T + wg_b  (single GEMM; f32 out)
    {
        dim3 grid(C_ / 64, L_ / 128, B_);
        gemm_mma<64, 0, 0, 0, 3, 64, 2><<<grid, 256, SM_64>>>(
            gpHi, gwgH, wg_b, gout2T, nullptr,
            L_, L_, L_, C_, (size_t)L_ * L_, (size_t)CL_, (size_t)CL_, 0, 0, 1.f);
    }

    // 5) LN1 -> h1 (f32 + f16)
    ln1_kernel<<<dim3(L_, B_), 256>>>(gout2T, gate, xt32, ln1_g, ln1_b, h1, h1Hi);

    // 6) MLP1: m1 = Mish(h1 @ conv1^T + b) -> f16
    {
        dim3 grid(C4_ / 128, NR_ / 128, 1);
        gemm_mma<128, 2, 1, 0, 2, 32, 2><<<grid, 256, SM_128>>>(
            h1Hi, c1W, conv1_b, nullptr, m1Hi,
            C_, C_, C_, C4_, 0, 0, 0, 0, 0, 1.f);
    }

    // 7) MLP2: m2 = m1 @ conv2^T + b -> f32
    {
        dim3 grid(C_ / 64, NR_ / 128, 1);
        gemm_mma<64, 0, 0, 0, 3, 64, 2><<<grid, 256, SM_64>>>(
            m1Hi, c2W, conv2_b, m2, nullptr,
            C4_, C4_, C4_, C_, 0, 0, 0, 0, 0, 1.f);
    }

    // 8) LN2: read-once + coalesced transpose out
    ln2_kernel<<<dim3(L_ / 32, B_), 256, LN2_SMEM>>>(m2, h1, ln2_g, ln2_b, out);
}